// round 13
// baseline (speedup 1.0000x reference)
#include <cuda_runtime.h>
#include <cuda_bf16.h>
#include <stdint.h>
#include <math.h>

// Problem constants
#define DM   1024
#define LSEQ 2048
#define BB   4
#define HH   256   // heads
#define HD   4     // head dim

typedef unsigned long long ull;

// ---------------- scratch (device globals; no allocs allowed) ----------------
__device__ float g_kkey [DM * LSEQ];
__device__ float g_kvker[HH * LSEQ];
__device__ float g_q [BB * DM * LSEQ];
__device__ float g_k [BB * DM * LSEQ];
__device__ float g_v [BB * DM * LSEQ];
__device__ float g_kc[BB * DM * LSEQ];
__device__ float g_y [BB * DM * LSEQ];
__device__ float g_bias[3 * DM];                // packed k/q/v bias (K first)
// bf16 split operands for tensor-core GEMMs; weight order: K, Q, V, PW
__device__ __nv_bfloat16 g_wh[4][DM * DM];
__device__ __nv_bfloat16 g_wl[4][DM * DM];
__device__ __nv_bfloat16 g_xh[BB * LSEQ * DM];
__device__ __nv_bfloat16 g_xl[BB * LSEQ * DM];

// ======================= helpers (baseline ISA only) =========================
__device__ __forceinline__ uint32_t smem_u32(const void* p) {
    uint32_t a;
    asm("{ .reg .u64 t; cvta.to.shared.u64 t, %1; cvt.u32.u64 %0, t; }" : "=r"(a) : "l"(p));
    return a;
}
__device__ __forceinline__ void cp16(uint32_t dst, const void* src) {
    asm volatile("cp.async.cg.shared.global [%0], [%1], 16;" :: "r"(dst), "l"(src));
}
__device__ __forceinline__ void ldsm4(uint32_t* r, uint32_t addr) {
    asm volatile("ldmatrix.sync.aligned.m8n8.x4.shared.b16 {%0,%1,%2,%3}, [%4];"
        : "=r"(r[0]), "=r"(r[1]), "=r"(r[2]), "=r"(r[3]) : "r"(addr));
}
__device__ __forceinline__ void mma16816(float* d, const uint32_t* a, const uint32_t* b) {
    asm volatile("mma.sync.aligned.m16n8k16.row.col.f32.bf16.bf16.f32 "
        "{%0,%1,%2,%3}, {%4,%5,%6,%7}, {%8,%9}, {%0,%1,%2,%3};"
        : "+f"(d[0]), "+f"(d[1]), "+f"(d[2]), "+f"(d[3])
        : "r"(a[0]), "r"(a[1]), "r"(a[2]), "r"(a[3]), "r"(b[0]), "r"(b[1]));
}
// ---------------- packed fp32x2 (Blackwell) ----------------
__device__ __forceinline__ ull pk2(float a, float b) {
    ull d; asm("mov.b64 %0, {%1, %2};" : "=l"(d) : "f"(a), "f"(b)); return d;
}
__device__ __forceinline__ ull mul2(ull a, ull b) {
    ull d; asm("mul.rn.f32x2 %0, %1, %2;" : "=l"(d) : "l"(a), "l"(b)); return d;
}
__device__ __forceinline__ ull fma2(ull a, ull b, ull c) {
    ull d; asm("fma.rn.f32x2 %0, %1, %2, %3;" : "=l"(d) : "l"(a), "l"(b), "l"(c)); return d;
}
__device__ __forceinline__ void upk2(ull v, float& a, float& b) {
    asm("mov.b64 {%0, %1}, %2;" : "=f"(a), "=f"(b) : "l"(v));
}

// =============================================================================
// Merged prep kernel: wsplit (blocks 0..16383), pack_bias (16384..16395),
// build_kernels (16396..17675).
// =============================================================================
__global__ void prep_all(const float* __restrict__ w0, const float* __restrict__ w1,
                         const float* __restrict__ w2, const float* __restrict__ w3,
                         __nv_bfloat16* __restrict__ h, __nv_bfloat16* __restrict__ l,
                         const float* __restrict__ kb, const float* __restrict__ qb,
                         const float* __restrict__ vb, float* __restrict__ biasd,
                         const float* __restrict__ src_key, const float* __restrict__ src_val,
                         float* __restrict__ dst_key, float* __restrict__ dst_val)
{
    const int bid = blockIdx.x;
    const int tid = threadIdx.x;

    if (bid < 16384) {                 // ---- wsplit4
        const int m = bid >> 12;
        const float* w = (m == 0) ? w0 : (m == 1) ? w1 : (m == 2) ? w2 : w3;
        int i = (bid & 4095) * 256 + tid;
        size_t o = (size_t)m * (DM * DM) + i;
        float x = w[i];
        __nv_bfloat16 hh = __float2bfloat16(x);
        h[o] = hh;
        l[o] = __float2bfloat16(x - __bfloat162float(hh));
        return;
    }
    if (bid < 16396) {                 // ---- pack_bias (order K,Q,V)
        int i = (bid - 16384) * 256 + tid;
        biasd[i] = (i < DM) ? kb[i] : (i < 2 * DM) ? qb[i - DM] : vb[i - 2 * DM];
        return;
    }
    // ---- build_kernels
    const int cc  = bid - 16396;
    const int c   = (cc < DM) ? cc : cc - DM;
    const int nch = (cc < DM) ? DM : HH;
    const float* src = (cc < DM) ? src_key : src_val;
    float* dst       = (cc < DM) ? dst_key : dst_val;
    float vals[8];
    float ss = 0.f;
    #pragma unroll
    for (int r = 0; r < 8; r++) {
        int j = tid * 8 + r;
        int i, start;
        if      (j <   64) { i = 0; start = 0;    }
        else if (j <  128) { i = 1; start = 64;   }
        else if (j <  256) { i = 2; start = 128;  }
        else if (j <  512) { i = 3; start = 256;  }
        else if (j < 1024) { i = 4; start = 512;  }
        else               { i = 5; start = 1024; }
        int   s    = (i <= 1) ? 1 : (1 << (i - 1));
        float mult = (float)(1 << (5 - i));
        int   jj   = j - start;
        float pos  = ((float)jj + 0.5f) / (float)s - 0.5f;
        pos = fminf(fmaxf(pos, 0.f), 63.f);
        int   lo = (int)floorf(pos);
        int   hi = min(lo + 1, 63);
        float w  = pos - (float)lo;
        const float* row = src + ((size_t)i * nch + c) * 64;
        float v = (row[lo] * (1.f - w) + row[hi] * w) * mult;
        vals[r] = v;
        ss += v * v;
    }
    __shared__ float red[256];
    red[tid] = ss;
    __syncthreads();
    for (int off = 128; off > 0; off >>= 1) {
        if (tid < off) red[tid] += red[tid + off];
        __syncthreads();
    }
    float inv = 1.f / sqrtf(red[0]);
    #pragma unroll
    for (int r = 0; r < 8; r++)
        dst[(size_t)c * LSEQ + tid * 8 + r] = vals[r] * inv;
}

// =============================================================================
// transpose (b, C, L) fp32 -> (b, L, C) bf16 hi/lo
// =============================================================================
__global__ void __launch_bounds__(256)
trans_split(const float* __restrict__ in, __nv_bfloat16* __restrict__ oh,
            __nv_bfloat16* __restrict__ ol)
{
    __shared__ float t[32][33];
    const int tx = threadIdx.x & 31, ty = threadIdx.x >> 5;
    const int l0 = blockIdx.x * 32, c0 = blockIdx.y * 32, b = blockIdx.z;
    #pragma unroll
    for (int i = 0; i < 4; i++) {
        int c = c0 + ty + i * 8;
        t[ty + i * 8][tx] = in[((size_t)b * DM + c) * LSEQ + l0 + tx];
    }
    __syncthreads();
    #pragma unroll
    for (int i = 0; i < 4; i++) {
        int l = l0 + ty + i * 8;
        float x = t[tx][ty + i * 8];
        __nv_bfloat16 h = __float2bfloat16(x);
        __nv_bfloat16 lo = __float2bfloat16(x - __bfloat162float(h));
        size_t o = ((size_t)b * LSEQ + l) * DM + c0 + tx;
        oh[o] = h; ol[o] = lo;
    }
}

// =============================================================================
// mma.sync bf16 split GEMM.  Tile 128x128, 256 threads, K-step 32 (SW64),
// 5-stage x 32KB cp.async ring (prefetch distance 4) = 160KB smem, 1 CTA/SM.
// =============================================================================
#define GSTG 32768

__device__ __forceinline__ void g_load_stage(
    uint32_t sbuf, int stage, int tid,
    const char* Wh, const char* Wl, const char* Xh, const char* Xl,
    size_t wrow0, size_t xrow0)
{
    const int k0b = stage * 64;           // 32 bf16 = 64 bytes
    const int c16 = (tid & 3) * 16;
    const int r0  = tid >> 2;             // 0..63
    #pragma unroll
    for (int t = 0; t < 4; t++) {
        const char* base = (t == 0) ? Wh : (t == 1) ? Wl : (t == 2) ? Xh : Xl;
        const size_t rowbase = (t < 2) ? wrow0 : xrow0;
        #pragma unroll
        for (int j = 0; j < 2; j++) {
            int row = r0 + j * 64;
            int off = row * 64 + c16;
            int sw  = off ^ ((off >> 3) & 0x30);   // SW64
            cp16(sbuf + t * 8192 + (uint32_t)sw,
                 base + rowbase + (size_t)row * 2048 + k0b + c16);
        }
    }
    asm volatile("cp.async.commit_group;" ::: "memory");
}

__device__ __forceinline__ void g_compute_stage(
    uint32_t sbuf, int lane, int warpM, int warpN, float acc[2][8][4])
{
    const uint32_t Ah = sbuf, Al = sbuf + 8192;
    const uint32_t Bh = sbuf + 16384, Bl = sbuf + 24576;
    #pragma unroll
    for (int kk = 0; kk < 2; kk++) {
        uint32_t ah[2][4], al[2][4], bh[8][2], bl[8][2];
        #pragma unroll
        for (int mt = 0; mt < 2; mt++) {
            int m  = warpM * 32 + mt * 16 + (lane & 15);
            int kb = kk * 32 + (lane >> 4) * 16;
            int off = m * 64 + kb;
            int sw  = off ^ ((off >> 3) & 0x30);
            ldsm4(ah[mt], Ah + sw);
            ldsm4(al[mt], Al + sw);
        }
        #pragma unroll
        for (int nb2 = 0; nb2 < 4; nb2++) {
            int n  = warpN * 64 + nb2 * 16 + (lane >> 4) * 8 + (lane & 7);
            int kb = kk * 32 + ((lane >> 3) & 1) * 16;
            int off = n * 64 + kb;
            int sw  = off ^ ((off >> 3) & 0x30);
            uint32_t r[4];
            ldsm4(r, Bh + sw);
            bh[nb2 * 2][0] = r[0]; bh[nb2 * 2][1] = r[1];
            bh[nb2 * 2 + 1][0] = r[2]; bh[nb2 * 2 + 1][1] = r[3];
            ldsm4(r, Bl + sw);
            bl[nb2 * 2][0] = r[0]; bl[nb2 * 2][1] = r[1];
            bl[nb2 * 2 + 1][0] = r[2]; bl[nb2 * 2 + 1][1] = r[3];
        }
        #pragma unroll
        for (int mt = 0; mt < 2; mt++)
            #pragma unroll
            for (int nb = 0; nb < 8; nb++) {
                mma16816(acc[mt][nb], ah[mt], bh[nb]);
                mma16816(acc[mt][nb], ah[mt], bl[nb]);
                mma16816(acc[mt][nb], al[mt], bh[nb]);
            }
    }
}

__global__ void __launch_bounds__(256, 1)
mma_gemm(const __nv_bfloat16* __restrict__ Wh, const __nv_bfloat16* __restrict__ Wl,
         const __nv_bfloat16* __restrict__ Xh, const __nv_bfloat16* __restrict__ Xl,
         const float* __restrict__ bias, int mbase,
         float* __restrict__ Y0, float* __restrict__ Y1, float* __restrict__ Y2)
{
    extern __shared__ char smem[];
    const uint32_t sb = smem_u32(smem);
    const int tid = threadIdx.x, wid = tid >> 5, lane = tid & 31;
    const int warpM = wid & 3, warpN = wid >> 2;       // 4M x 2N warp grid
    const int n0 = blockIdx.x * 128, m0 = mbase + blockIdx.y * 128, b = blockIdx.z;
    const size_t wrow0 = (size_t)m0 * 2048;
    const size_t xrow0 = ((size_t)b * LSEQ + n0) * 2048;
    const char* cWh = (const char*)Wh; const char* cWl = (const char*)Wl;
    const char* cXh = (const char*)Xh; const char* cXl = (const char*)Xl;

    float acc[2][8][4];
    #pragma unroll
    for (int mt = 0; mt < 2; mt++)
        #pragma unroll
        for (int nb = 0; nb < 8; nb++)
            #pragma unroll
            for (int j = 0; j < 4; j++) acc[mt][nb][j] = 0.f;

    #pragma unroll
    for (int s = 0; s < 5; s++)
        g_load_stage(sb + s * GSTG, s, tid, cWh, cWl, cXh, cXl, wrow0, xrow0);

    int slot = 0;
    for (int st = 0; st < 32; st++) {
        // prefetch distance 4: wait until stage st's group has landed
        if (st <= 27)      asm volatile("cp.async.wait_group 4;" ::: "memory");
        else if (st == 28) asm volatile("cp.async.wait_group 3;" ::: "memory");
        else if (st == 29) asm volatile("cp.async.wait_group 2;" ::: "memory");
        else if (st == 30) asm volatile("cp.async.wait_group 1;" ::: "memory");
        else               asm volatile("cp.async.wait_group 0;" ::: "memory");
        __syncthreads();
        g_compute_stage(sb + slot * GSTG, lane, warpM, warpN, acc);
        __syncthreads();
        if (st + 5 < 32)
            g_load_stage(sb + slot * GSTG, st + 5, tid, cWh, cWl, cXh, cXl, wrow0, xrow0);
        slot = (slot == 4) ? 0 : slot + 1;
    }

    const int mat = m0 >> 10;
    float* Y = (mat == 0) ? Y0 : (mat == 1) ? Y1 : Y2;
    const int rq = lane >> 2;
    const int cq = (lane & 3) * 2;
    #pragma unroll
    for (int mt = 0; mt < 2; mt++) {
        const int rs = m0 + warpM * 32 + mt * 16 + rq;
        const int row = rs & 1023;
        const float b0 = bias[rs], b1 = bias[rs + 8];
        const size_t y0 = ((size_t)b * DM + row) * LSEQ;
        #pragma unroll
        for (int nb = 0; nb < 8; nb++) {
            const int col = n0 + warpN * 64 + nb * 8 + cq;
            float2 v0, v1;
            v0.x = acc[mt][nb][0] + b0; v0.y = acc[mt][nb][1] + b0;
            v1.x = acc[mt][nb][2] + b1; v1.y = acc[mt][nb][3] + b1;
            *(float2*)&Y[y0 + col] = v0;
            *(float2*)&Y[y0 + 8 * LSEQ + col] = v1;
        }
    }
}

// =============================================================================
// Kernel C: per-channel causal long conv (dkey folded into kernel lag 0)
// =============================================================================
__global__ void __launch_bounds__(256)
keyconv_kernel(const float* __restrict__ kk, const float* __restrict__ kker,
               const float* __restrict__ dkey, float* __restrict__ out)
{
    extern __shared__ float dsm[];
    float* xp0 = dsm;
    float* xp1 = dsm + 4608;
    float* ks0 = dsm + 9216;
    float* ks1 = dsm + 11264;
    const int c0 = blockIdx.x * 2, b = blockIdx.y;
    const int tid = threadIdx.x;
    const size_t rb0 = ((size_t)b * DM + c0) * LSEQ;
    const size_t rb1 = rb0 + LSEQ;

    for (int i = tid; i < 4608; i += 256) { xp0[i] = 0.f; xp1[i] = 0.f; }
    __syncthreads();
    for (int i = tid; i < 2048; i += 256) {
        float add0 = (i == 0) ? dkey[c0] : 0.f;
        float add1 = (i == 0) ? dkey[c0 + 1] : 0.f;
        ks0[i] = kker[(size_t)c0 * LSEQ + i] + add0;
        ks1[i] = kker[(size_t)(c0 + 1) * LSEQ + i] + add1;
        int p = 2048 + i;
        int a = p + (p >> 4);
        xp0[a] = kk[rb0 + i];
        xp1[a] = kk[rb1 + i];
    }
    __syncthreads();

    const int wid = tid >> 5, lane = tid & 31;
    const int ch = (wid < 4) ? 0 : 1;
    const int strip = (wid < 4) ? wid : (7 - wid);
    float* X = ch ? xp1 : xp0;
    float* K = ch ? ks1 : ks0;
    const size_t rowbase = ch ? rb1 : rb0;
    const int l0 = strip * 512 + lane * 16;
    const int jmax = strip * 512 + 511;

    ull acc2[8];
    #pragma unroll
    for (int r2 = 0; r2 < 8; r2++) acc2[r2] = 0ull;

    for (int j0 = 0; j0 <= jmax; j0 += 8) {
        float4 kA = *(const float4*)&K[j0];
        float4 kB = *(const float4*)&K[j0 + 4];
        ull kr2[8];
        kr2[0] = pk2(kA.x, kA.x); kr2[1] = pk2(kA.y, kA.y);
        kr2[2] = pk2(kA.z, kA.z); kr2[3] = pk2(kA.w, kA.w);
        kr2[4] = pk2(kB.x, kB.x); kr2[5] = pk2(kB.y, kB.y);
        kr2[6] = pk2(kB.z, kB.z); kr2[7] = pk2(kB.w, kB.w);
        float xv[23];
        #pragma unroll
        for (int t = 0; t < 23; t++) {
            int p = 2048 + l0 - j0 - 7 + t;
            xv[t] = X[p + (p >> 4)];
        }
        ull xv2[22];
        #pragma unroll
        for (int t = 0; t < 22; t++) xv2[t] = pk2(xv[t], xv[t + 1]);
        #pragma unroll
        for (int r2 = 0; r2 < 8; r2++)
            #pragma unroll
            for (int s = 0; s < 8; s++)
                acc2[r2] = fma2(kr2[s], xv2[2 * r2 - s + 7], acc2[r2]);
    }
    #pragma unroll
    for (int r2 = 0; r2 < 8; r2++) {
        float a0, a1;
        upk2(acc2[r2], a0, a1);
        out[rowbase + l0 + 2 * r2]     = a0;
        out[rowbase + l0 + 2 * r2 + 1] = a1;
    }
}

// =============================================================================
// Kernel D: kernel-weighted linear attention (D folded into ker lag 0)
// =============================================================================
__global__ void __launch_bounds__(256)
attn_kernel(const float* __restrict__ gq, const float* __restrict__ gk,
            const float* __restrict__ gv, const float* __restrict__ kerv,
            const float* __restrict__ Dp, float* __restrict__ gy)
{
    extern __shared__ float sm[];
    float* ks = sm;
    float* vs = sm + 8192;
    float* kp = sm + 16384;
    const int h = blockIdx.x, b = blockIdx.y;
    const int tid = threadIdx.x;
    const size_t base = ((size_t)b * DM + (size_t)h * HD) * LSEQ;

    for (int i = tid; i < 8192; i += 256) { ks[i] = gk[base + i]; vs[i] = gv[base + i]; }
    for (int i = tid; i < 4608; i += 256) kp[i] = 0.f;
    __syncthreads();
    for (int j = tid; j < 2048; j += 256) {
        int p = 2048 + j;
        float add = (j == 0) ? Dp[h] : 0.f;
        kp[p + (p >> 3)] = kerv[(size_t)h * LSEQ + j] + add;
    }
    __syncthreads();

    const int wid = tid >> 5, lane = tid & 31;
    const int strip = (wid < 4) ? wid : (11 - wid);
    const int l0 = strip * 256 + lane * 8;
    const int mmax = strip * 256 + 255;

    ull q2[4][4];
    #pragma unroll
    for (int d1 = 0; d1 < 4; d1++)
        #pragma unroll
        for (int r2 = 0; r2 < 4; r2++) {
            float2 qq = *(const float2*)&gq[base + (size_t)d1 * LSEQ + l0 + 2 * r2];
            q2[d1][r2] = pk2(qq.x, qq.y);
        }

    ull acc2[4][4];
    #pragma unroll
    for (int d = 0; d < 4; d++)
        #pragma unroll
        for (int r2 = 0; r2 < 4; r2++) acc2[d][r2] = 0ull;

    const int pb = 2048 + l0;

    for (int mb = 0; mb <= mmax; mb += 4) {
        float4 kf0 = *(const float4*)&ks[mb];
        float4 kf1 = *(const float4*)&ks[2048 + mb];
        float4 kf2 = *(const float4*)&ks[4096 + mb];
        float4 kf3 = *(const float4*)&ks[6144 + mb];
        float4 vf0 = *(const float4*)&vs[mb];
        float4 vf1 = *(const float4*)&vs[2048 + mb];
        float4 vf2 = *(const float4*)&vs[4096 + mb];
        float4 vf3 = *(const float4*)&vs[6144 + mb];
        float ka[4][4] = {{kf0.x,kf0.y,kf0.z,kf0.w},{kf1.x,kf1.y,kf1.z,kf1.w},
                          {kf2.x,kf2.y,kf2.z,kf2.w},{kf3.x,kf3.y,kf3.z,kf3.w}};
        float va[4][4] = {{vf0.x,vf0.y,vf0.z,vf0.w},{vf1.x,vf1.y,vf1.z,vf1.w},
                          {vf2.x,vf2.y,vf2.z,vf2.w},{vf3.x,vf3.y,vf3.z,vf3.w}};
        float w11[11];
        #pragma unroll
        for (int t = 0; t < 11; t++) {
            int p = pb - mb - 3 + t;
            w11[t] = kp[p + (p >> 3)];
        }
        #pragma unroll
        for (int i = 0; i < 4; i++) {
            ull kk0 = pk2(ka[0][i], ka[0][i]), kk1 = pk2(ka[1][i], ka[1][i]);
            ull kk2 = pk2(ka[2][i], ka[2][i]), kk3 = pk2(ka[3][i], ka[3][i]);
            ull vv0 = pk2(va[0][i], va[0][i]), vv1 = pk2(va[1][i], va[1][i]);
            ull vv2 = pk2(va[2][i], va[2][i]), vv3 = pk2(va[3][i], va[3][i]);
            #pragma unroll
            for (int r2 = 0; r2 < 4; r2++) {
                ull s = mul2(q2[0][r2], kk0);
                s = fma2(q2[1][r2], kk1, s);
                s = fma2(q2[2][r2], kk2, s);
                s = fma2(q2[3][r2], kk3, s);
                ull kerp = pk2(w11[2 * r2 - i + 3], w11[2 * r2 - i + 4]);
                ull w = mul2(s, kerp);
                acc2[0][r2] = fma2(w, vv0, acc2[0][r2]);
                acc2[1][r2] = fma2(w, vv1, acc2[1][r2]);
                acc2[2][r2] = fma2(w, vv2, acc2[2][r2]);
                acc2[3][r2] = fma2(w, vv3, acc2[3][r2]);
            }
        }
    }

    float acc[4][8];
    #pragma unroll
    for (int d = 0; d < 4; d++)
        #pragma unroll
        for (int r2 = 0; r2 < 4; r2++)
            upk2(acc2[d][r2], acc[d][2 * r2], acc[d][2 * r2 + 1]);

    #pragma unroll
    for (int d2 = 0; d2 < 4; d2++) {
        size_t orow = ((size_t)b * DM + (size_t)d2 * HH + h) * LSEQ + l0;
        #pragma unroll
        for (int r = 0; r < 8; r++) {
            float x = acc[d2][r];
            gy[orow + r] = 0.5f * x * (1.f + erff(x * 0.70710678118654752f));
        }
    }
}

// =============================================================================
extern "C" void kernel_launch(void* const* d_in, const int* in_sizes, int n_in,
                              void* d_out, int out_size)
{
    const float* u       = (const float*)d_in[0];
    const float* q_w     = (const float*)d_in[1];
    const float* q_b     = (const float*)d_in[2];
    const float* k_w     = (const float*)d_in[3];
    const float* k_b     = (const float*)d_in[4];
    const float* v_w     = (const float*)d_in[5];
    const float* v_b     = (const float*)d_in[6];
    const float* kkey_in = (const float*)d_in[7];
    const float* kv_in   = (const float*)d_in[8];
    const float* D_key   = (const float*)d_in[9];
    const float* Dh      = (const float*)d_in[10];
    const float* pw_w    = (const float*)d_in[11];
    const float* pw_b    = (const float*)d_in[12];
    float* out = (float*)d_out;

    float *kkey, *kvk, *q, *k, *v, *kc, *y, *bias;
    __nv_bfloat16 *wh, *wl, *xh, *xl;
    cudaGetSymbolAddress((void**)&kkey, g_kkey);
    cudaGetSymbolAddress((void**)&kvk,  g_kvker);
    cudaGetSymbolAddress((void**)&q,    g_q);
    cudaGetSymbolAddress((void**)&k,    g_k);
    cudaGetSymbolAddress((void**)&v,    g_v);
    cudaGetSymbolAddress((void**)&kc,   g_kc);
    cudaGetSymbolAddress((void**)&y,    g_y);
    cudaGetSymbolAddress((void**)&bias, g_bias);
    cudaGetSymbolAddress((void**)&wh,   g_wh);
    cudaGetSymbolAddress((void**)&wl,   g_wl);
    cudaGetSymbolAddress((void**)&xh,   g_xh);
    cudaGetSymbolAddress((void**)&xl,   g_xl);

    const int ATT_SMEM = (8192 + 8192 + 4608) * (int)sizeof(float);   // 83968
    const int KC_SMEM  = (2 * 4608 + 2 * 2048) * (int)sizeof(float);  // 53248
    cudaFuncSetAttribute(attn_kernel, cudaFuncAttributeMaxDynamicSharedMemorySize, ATT_SMEM);
    cudaFuncSetAttribute(keyconv_kernel, cudaFuncAttributeMaxDynamicSharedMemorySize, KC_SMEM);
    cudaFuncSetAttribute(mma_gemm, cudaFuncAttributeMaxDynamicSharedMemorySize, 5 * GSTG);

    const size_t WN = (size_t)DM * DM;

    // Launch order: keyconv is the 4th launch (= the one ncu captures).
    prep_all<<<17676, 256>>>(k_w, q_w, v_w, pw_w, wh, wl,
                             k_b, q_b, v_b, bias,
                             kkey_in, kv_in, kkey, kvk);                 // 1
    trans_split<<<dim3(LSEQ / 32, DM / 32, BB), 256>>>(u, xh, xl);       // 2
    mma_gemm<<<dim3(LSEQ / 128, 24, BB), 256, 5 * GSTG>>>(               // 3
        wh, wl, xh, xl, bias, 0, k, q, v);
    keyconv_kernel<<<dim3(DM / 2, BB), 256, KC_SMEM>>>(k, kkey, D_key, kc); // 4 (profiled)
    attn_kernel<<<dim3(HH, BB), 256, ATT_SMEM>>>(q, kc, v, kvk, Dh, y);  // 5
    trans_split<<<dim3(LSEQ / 32, DM / 32, BB), 256>>>(y, xh, xl);       // 6
    mma_gemm<<<dim3(LSEQ / 128, 8, BB), 256, 5 * GSTG>>>(                // 7
        wh + 3 * WN, wl + 3 * WN, xh, xl, pw_b, 0, out, out, out);
}

// round 14
// speedup vs baseline: 1.1493x; 1.1493x over previous
#include <cuda_runtime.h>
#include <cuda_bf16.h>
#include <stdint.h>
#include <math.h>

// Problem constants
#define DM   1024
#define LSEQ 2048
#define BB   4
#define HH   256   // heads
#define HD   4     // head dim

typedef unsigned long long ull;

// ---------------- scratch (device globals; no allocs allowed) ----------------
__device__ float g_kkey [DM * LSEQ];
__device__ float g_kvker[HH * LSEQ];
__device__ float g_q [BB * DM * LSEQ];
__device__ float g_k [BB * DM * LSEQ];
__device__ float g_v [BB * DM * LSEQ];
__device__ float g_kc[BB * DM * LSEQ];
__device__ float g_y [BB * DM * LSEQ];
__device__ float g_bias[3 * DM];                // packed k/q/v bias (K first)
// bf16 split operands for tensor-core GEMMs; weight order: K, Q, V, PW
__device__ __nv_bfloat16 g_wh[4][DM * DM];
__device__ __nv_bfloat16 g_wl[4][DM * DM];
__device__ __nv_bfloat16 g_xh[BB * LSEQ * DM];
__device__ __nv_bfloat16 g_xl[BB * LSEQ * DM];

// ======================= helpers (baseline ISA only) =========================
__device__ __forceinline__ uint32_t smem_u32(const void* p) {
    uint32_t a;
    asm("{ .reg .u64 t; cvta.to.shared.u64 t, %1; cvt.u32.u64 %0, t; }" : "=r"(a) : "l"(p));
    return a;
}
__device__ __forceinline__ void cp16(uint32_t dst, const void* src) {
    asm volatile("cp.async.cg.shared.global [%0], [%1], 16;" :: "r"(dst), "l"(src));
}
__device__ __forceinline__ void ldsm4(uint32_t* r, uint32_t addr) {
    asm volatile("ldmatrix.sync.aligned.m8n8.x4.shared.b16 {%0,%1,%2,%3}, [%4];"
        : "=r"(r[0]), "=r"(r[1]), "=r"(r[2]), "=r"(r[3]) : "r"(addr));
}
__device__ __forceinline__ void mma16816(float* d, const uint32_t* a, const uint32_t* b) {
    asm volatile("mma.sync.aligned.m16n8k16.row.col.f32.bf16.bf16.f32 "
        "{%0,%1,%2,%3}, {%4,%5,%6,%7}, {%8,%9}, {%0,%1,%2,%3};"
        : "+f"(d[0]), "+f"(d[1]), "+f"(d[2]), "+f"(d[3])
        : "r"(a[0]), "r"(a[1]), "r"(a[2]), "r"(a[3]), "r"(b[0]), "r"(b[1]));
}
// ---------------- packed fp32x2 (Blackwell) ----------------
__device__ __forceinline__ ull pk2(float a, float b) {
    ull d; asm("mov.b64 %0, {%1, %2};" : "=l"(d) : "f"(a), "f"(b)); return d;
}
__device__ __forceinline__ ull mul2(ull a, ull b) {
    ull d; asm("mul.rn.f32x2 %0, %1, %2;" : "=l"(d) : "l"(a), "l"(b)); return d;
}
__device__ __forceinline__ ull fma2(ull a, ull b, ull c) {
    ull d; asm("fma.rn.f32x2 %0, %1, %2, %3;" : "=l"(d) : "l"(a), "l"(b), "l"(c)); return d;
}
__device__ __forceinline__ void upk2(ull v, float& a, float& b) {
    asm("mov.b64 {%0, %1}, %2;" : "=f"(a), "=f"(b) : "l"(v));
}

// =============================================================================
// Merged prep kernel: wsplit (blocks 0..16383), pack_bias (16384..16395),
// build_kernels (16396..17675).
// =============================================================================
__global__ void prep_all(const float* __restrict__ w0, const float* __restrict__ w1,
                         const float* __restrict__ w2, const float* __restrict__ w3,
                         __nv_bfloat16* __restrict__ h, __nv_bfloat16* __restrict__ l,
                         const float* __restrict__ kb, const float* __restrict__ qb,
                         const float* __restrict__ vb, float* __restrict__ biasd,
                         const float* __restrict__ src_key, const float* __restrict__ src_val,
                         float* __restrict__ dst_key, float* __restrict__ dst_val)
{
    const int bid = blockIdx.x;
    const int tid = threadIdx.x;

    if (bid < 16384) {                 // ---- wsplit4
        const int m = bid >> 12;
        const float* w = (m == 0) ? w0 : (m == 1) ? w1 : (m == 2) ? w2 : w3;
        int i = (bid & 4095) * 256 + tid;
        size_t o = (size_t)m * (DM * DM) + i;
        float x = w[i];
        __nv_bfloat16 hh = __float2bfloat16(x);
        h[o] = hh;
        l[o] = __float2bfloat16(x - __bfloat162float(hh));
        return;
    }
    if (bid < 16396) {                 // ---- pack_bias (order K,Q,V)
        int i = (bid - 16384) * 256 + tid;
        biasd[i] = (i < DM) ? kb[i] : (i < 2 * DM) ? qb[i - DM] : vb[i - 2 * DM];
        return;
    }
    // ---- build_kernels
    const int cc  = bid - 16396;
    const int c   = (cc < DM) ? cc : cc - DM;
    const int nch = (cc < DM) ? DM : HH;
    const float* src = (cc < DM) ? src_key : src_val;
    float* dst       = (cc < DM) ? dst_key : dst_val;
    float vals[8];
    float ss = 0.f;
    #pragma unroll
    for (int r = 0; r < 8; r++) {
        int j = tid * 8 + r;
        int i, start;
        if      (j <   64) { i = 0; start = 0;    }
        else if (j <  128) { i = 1; start = 64;   }
        else if (j <  256) { i = 2; start = 128;  }
        else if (j <  512) { i = 3; start = 256;  }
        else if (j < 1024) { i = 4; start = 512;  }
        else               { i = 5; start = 1024; }
        int   s    = (i <= 1) ? 1 : (1 << (i - 1));
        float mult = (float)(1 << (5 - i));
        int   jj   = j - start;
        float pos  = ((float)jj + 0.5f) / (float)s - 0.5f;
        pos = fminf(fmaxf(pos, 0.f), 63.f);
        int   lo = (int)floorf(pos);
        int   hi = min(lo + 1, 63);
        float w  = pos - (float)lo;
        const float* row = src + ((size_t)i * nch + c) * 64;
        float v = (row[lo] * (1.f - w) + row[hi] * w) * mult;
        vals[r] = v;
        ss += v * v;
    }
    __shared__ float red[256];
    red[tid] = ss;
    __syncthreads();
    for (int off = 128; off > 0; off >>= 1) {
        if (tid < off) red[tid] += red[tid + off];
        __syncthreads();
    }
    float inv = 1.f / sqrtf(red[0]);
    #pragma unroll
    for (int r = 0; r < 8; r++)
        dst[(size_t)c * LSEQ + tid * 8 + r] = vals[r] * inv;
}

// =============================================================================
// transpose (b, C, L) fp32 -> (b, L, C) bf16 hi/lo
// =============================================================================
__global__ void __launch_bounds__(256)
trans_split(const float* __restrict__ in, __nv_bfloat16* __restrict__ oh,
            __nv_bfloat16* __restrict__ ol)
{
    __shared__ float t[32][33];
    const int tx = threadIdx.x & 31, ty = threadIdx.x >> 5;
    const int l0 = blockIdx.x * 32, c0 = blockIdx.y * 32, b = blockIdx.z;
    #pragma unroll
    for (int i = 0; i < 4; i++) {
        int c = c0 + ty + i * 8;
        t[ty + i * 8][tx] = in[((size_t)b * DM + c) * LSEQ + l0 + tx];
    }
    __syncthreads();
    #pragma unroll
    for (int i = 0; i < 4; i++) {
        int l = l0 + ty + i * 8;
        float x = t[tx][ty + i * 8];
        __nv_bfloat16 h = __float2bfloat16(x);
        __nv_bfloat16 lo = __float2bfloat16(x - __bfloat162float(h));
        size_t o = ((size_t)b * LSEQ + l) * DM + c0 + tx;
        oh[o] = h; ol[o] = lo;
    }
}

// =============================================================================
// mma.sync bf16 split GEMM — R12 config (measured qkv 375us).
// Tile 128x128, 256 thr, K-step 32 (SW64), 3-stage x 32KB ring.
// =============================================================================
#define GSTG 32768

__device__ __forceinline__ void g_load_stage(
    uint32_t sbuf, int stage, int tid,
    const char* Wh, const char* Wl, const char* Xh, const char* Xl,
    size_t wrow0, size_t xrow0)
{
    const int k0b = stage * 64;
    const int c16 = (tid & 3) * 16;
    const int r0  = tid >> 2;
    #pragma unroll
    for (int t = 0; t < 4; t++) {
        const char* base = (t == 0) ? Wh : (t == 1) ? Wl : (t == 2) ? Xh : Xl;
        const size_t rowbase = (t < 2) ? wrow0 : xrow0;
        #pragma unroll
        for (int j = 0; j < 2; j++) {
            int row = r0 + j * 64;
            int off = row * 64 + c16;
            int sw  = off ^ ((off >> 3) & 0x30);   // SW64
            cp16(sbuf + t * 8192 + (uint32_t)sw,
                 base + rowbase + (size_t)row * 2048 + k0b + c16);
        }
    }
    asm volatile("cp.async.commit_group;" ::: "memory");
}

__device__ __forceinline__ void g_compute_stage(
    uint32_t sbuf, int lane, int warpM, int warpN, float acc[2][8][4])
{
    const uint32_t Ah = sbuf, Al = sbuf + 8192;
    const uint32_t Bh = sbuf + 16384, Bl = sbuf + 24576;
    #pragma unroll
    for (int kk = 0; kk < 2; kk++) {
        uint32_t ah[2][4], al[2][4], bh[8][2], bl[8][2];
        #pragma unroll
        for (int mt = 0; mt < 2; mt++) {
            int m  = warpM * 32 + mt * 16 + (lane & 15);
            int kb = kk * 32 + (lane >> 4) * 16;
            int off = m * 64 + kb;
            int sw  = off ^ ((off >> 3) & 0x30);
            ldsm4(ah[mt], Ah + sw);
            ldsm4(al[mt], Al + sw);
        }
        #pragma unroll
        for (int nb2 = 0; nb2 < 4; nb2++) {
            int n  = warpN * 64 + nb2 * 16 + (lane >> 4) * 8 + (lane & 7);
            int kb = kk * 32 + ((lane >> 3) & 1) * 16;
            int off = n * 64 + kb;
            int sw  = off ^ ((off >> 3) & 0x30);
            uint32_t r[4];
            ldsm4(r, Bh + sw);
            bh[nb2 * 2][0] = r[0]; bh[nb2 * 2][1] = r[1];
            bh[nb2 * 2 + 1][0] = r[2]; bh[nb2 * 2 + 1][1] = r[3];
            ldsm4(r, Bl + sw);
            bl[nb2 * 2][0] = r[0]; bl[nb2 * 2][1] = r[1];
            bl[nb2 * 2 + 1][0] = r[2]; bl[nb2 * 2 + 1][1] = r[3];
        }
        #pragma unroll
        for (int mt = 0; mt < 2; mt++)
            #pragma unroll
            for (int nb = 0; nb < 8; nb++) {
                mma16816(acc[mt][nb], ah[mt], bh[nb]);
                mma16816(acc[mt][nb], ah[mt], bl[nb]);
                mma16816(acc[mt][nb], al[mt], bh[nb]);
            }
    }
}

__global__ void __launch_bounds__(256, 2)
mma_gemm(const __nv_bfloat16* __restrict__ Wh, const __nv_bfloat16* __restrict__ Wl,
         const __nv_bfloat16* __restrict__ Xh, const __nv_bfloat16* __restrict__ Xl,
         const float* __restrict__ bias, int mbase,
         float* __restrict__ Y0, float* __restrict__ Y1, float* __restrict__ Y2)
{
    extern __shared__ char smem[];
    const uint32_t sb = smem_u32(smem);
    const int tid = threadIdx.x, wid = tid >> 5, lane = tid & 31;
    const int warpM = wid & 3, warpN = wid >> 2;
    const int n0 = blockIdx.x * 128, m0 = mbase + blockIdx.y * 128, b = blockIdx.z;
    const size_t wrow0 = (size_t)m0 * 2048;
    const size_t xrow0 = ((size_t)b * LSEQ + n0) * 2048;
    const char* cWh = (const char*)Wh; const char* cWl = (const char*)Wl;
    const char* cXh = (const char*)Xh; const char* cXl = (const char*)Xl;

    float acc[2][8][4];
    #pragma unroll
    for (int mt = 0; mt < 2; mt++)
        #pragma unroll
        for (int nb = 0; nb < 8; nb++)
            #pragma unroll
            for (int j = 0; j < 4; j++) acc[mt][nb][j] = 0.f;

    g_load_stage(sb,            0, tid, cWh, cWl, cXh, cXl, wrow0, xrow0);
    g_load_stage(sb + GSTG,     1, tid, cWh, cWl, cXh, cXl, wrow0, xrow0);
    g_load_stage(sb + 2 * GSTG, 2, tid, cWh, cWl, cXh, cXl, wrow0, xrow0);

    int slot = 0;
    for (int st = 0; st < 32; st++) {
        if (st <= 29)      asm volatile("cp.async.wait_group 2;" ::: "memory");
        else if (st == 30) asm volatile("cp.async.wait_group 1;" ::: "memory");
        else               asm volatile("cp.async.wait_group 0;" ::: "memory");
        __syncthreads();
        g_compute_stage(sb + slot * GSTG, lane, warpM, warpN, acc);
        __syncthreads();
        if (st + 3 < 32)
            g_load_stage(sb + slot * GSTG, st + 3, tid, cWh, cWl, cXh, cXl, wrow0, xrow0);
        slot = (slot == 2) ? 0 : slot + 1;
    }

    const int mat = m0 >> 10;
    float* Y = (mat == 0) ? Y0 : (mat == 1) ? Y1 : Y2;
    const int rq = lane >> 2;
    const int cq = (lane & 3) * 2;
    #pragma unroll
    for (int mt = 0; mt < 2; mt++) {
        const int rs = m0 + warpM * 32 + mt * 16 + rq;
        const int row = rs & 1023;
        const float b0 = bias[rs], b1 = bias[rs + 8];
        const size_t y0 = ((size_t)b * DM + row) * LSEQ;
        #pragma unroll
        for (int nb = 0; nb < 8; nb++) {
            const int col = n0 + warpN * 64 + nb * 8 + cq;
            float2 v0, v1;
            v0.x = acc[mt][nb][0] + b0; v0.y = acc[mt][nb][1] + b0;
            v1.x = acc[mt][nb][2] + b1; v1.y = acc[mt][nb][3] + b1;
            *(float2*)&Y[y0 + col] = v0;
            *(float2*)&Y[y0 + 8 * LSEQ + col] = v1;
        }
    }
}

// =============================================================================
// Kernel C: causal long conv (dkey folded).  j-loop unrolled by 16 so the
// padded gather becomes a sliding base pointer (-17 floats / iter) with
// COMPILE-TIME offsets off(t) = t + (t>=15): 31 LDS + 1 IADD per 16 j
// replaces 46 LDS + ~46 ALU.  Accumulation order unchanged (bit-identical).
// =============================================================================
__global__ void __launch_bounds__(256)
keyconv_kernel(const float* __restrict__ kk, const float* __restrict__ kker,
               const float* __restrict__ dkey, float* __restrict__ out)
{
    extern __shared__ float dsm[];
    float* xp0 = dsm;
    float* xp1 = dsm + 4608;
    float* ks0 = dsm + 9216;
    float* ks1 = dsm + 11264;
    const int c0 = blockIdx.x * 2, b = blockIdx.y;
    const int tid = threadIdx.x;
    const size_t rb0 = ((size_t)b * DM + c0) * LSEQ;
    const size_t rb1 = rb0 + LSEQ;

    for (int i = tid; i < 4608; i += 256) { xp0[i] = 0.f; xp1[i] = 0.f; }
    __syncthreads();
    for (int i = tid; i < 2048; i += 256) {
        float add0 = (i == 0) ? dkey[c0] : 0.f;
        float add1 = (i == 0) ? dkey[c0 + 1] : 0.f;
        ks0[i] = kker[(size_t)c0 * LSEQ + i] + add0;
        ks1[i] = kker[(size_t)(c0 + 1) * LSEQ + i] + add1;
        int p = 2048 + i;
        int a = p + (p >> 4);
        xp0[a] = kk[rb0 + i];
        xp1[a] = kk[rb1 + i];
    }
    __syncthreads();

    const int wid = tid >> 5, lane = tid & 31;
    const int ch = (wid < 4) ? 0 : 1;
    const int strip = (wid < 4) ? wid : (7 - wid);
    float* X = ch ? xp1 : xp0;
    float* K = ch ? ks1 : ks0;
    const size_t rowbase = ch ? rb1 : rb0;
    const int l0 = strip * 512 + lane * 16;
    const int jmax = strip * 512 + 511;

    ull acc2[8];
    #pragma unroll
    for (int r2 = 0; r2 < 8; r2++) acc2[r2] = 0ull;

    // sliding window base: W0 = 2048 + l0 - 15 (≡ 1 mod 16); a(W0) = W0 + (W0>>4)
    int W0 = 2048 + l0 - 15;
    const float* Bf = X + (W0 + (W0 >> 4));

    for (int j0 = 0; j0 <= jmax; j0 += 16) {
        float xv[31];
        #pragma unroll
        for (int t = 0; t < 31; t++) xv[t] = Bf[t + (t >= 15 ? 1 : 0)];
        ull xv2[30];
        #pragma unroll
        for (int t = 0; t < 30; t++) xv2[t] = pk2(xv[t], xv[t + 1]);

        // sub-chunk A: j in [j0, j0+7], window offset +8
        {
            float4 kA = *(const float4*)&K[j0];
            float4 kB = *(const float4*)&K[j0 + 4];
            ull kr2[8];
            kr2[0] = pk2(kA.x, kA.x); kr2[1] = pk2(kA.y, kA.y);
            kr2[2] = pk2(kA.z, kA.z); kr2[3] = pk2(kA.w, kA.w);
            kr2[4] = pk2(kB.x, kB.x); kr2[5] = pk2(kB.y, kB.y);
            kr2[6] = pk2(kB.z, kB.z); kr2[7] = pk2(kB.w, kB.w);
            #pragma unroll
            for (int r2 = 0; r2 < 8; r2++)
                #pragma unroll
                for (int s = 0; s < 8; s++)
                    acc2[r2] = fma2(kr2[s], xv2[2 * r2 - s + 15], acc2[r2]);
        }
        // sub-chunk B: j in [j0+8, j0+15], window offset 0
        {
            float4 kA = *(const float4*)&K[j0 + 8];
            float4 kB = *(const float4*)&K[j0 + 12];
            ull kr2[8];
            kr2[0] = pk2(kA.x, kA.x); kr2[1] = pk2(kA.y, kA.y);
            kr2[2] = pk2(kA.z, kA.z); kr2[3] = pk2(kA.w, kA.w);
            kr2[4] = pk2(kB.x, kB.x); kr2[5] = pk2(kB.y, kB.y);
            kr2[6] = pk2(kB.z, kB.z); kr2[7] = pk2(kB.w, kB.w);
            #pragma unroll
            for (int r2 = 0; r2 < 8; r2++)
                #pragma unroll
                for (int s = 0; s < 8; s++)
                    acc2[r2] = fma2(kr2[s], xv2[2 * r2 - s + 7], acc2[r2]);
        }
        Bf -= 17;
    }
    #pragma unroll
    for (int r2 = 0; r2 < 8; r2++) {
        float a0, a1;
        upk2(acc2[r2], a0, a1);
        out[rowbase + l0 + 2 * r2]     = a0;
        out[rowbase + l0 + 2 * r2 + 1] = a1;
    }
}

// =============================================================================
// Kernel D: kernel-weighted linear attention (D folded).  m-loop unrolled by 8;
// ker gather = sliding base (-9 floats / iter) with compile-time offsets
// off(t) = t + (t>=7), shared 15-value window for both 4-m sub-chunks.
// =============================================================================
__global__ void __launch_bounds__(256)
attn_kernel(const float* __restrict__ gq, const float* __restrict__ gk,
            const float* __restrict__ gv, const float* __restrict__ kerv,
            const float* __restrict__ Dp, float* __restrict__ gy)
{
    extern __shared__ float sm[];
    float* ks = sm;
    float* vs = sm + 8192;
    float* kp = sm + 16384;
    const int h = blockIdx.x, b = blockIdx.y;
    const int tid = threadIdx.x;
    const size_t base = ((size_t)b * DM + (size_t)h * HD) * LSEQ;

    for (int i = tid; i < 8192; i += 256) { ks[i] = gk[base + i]; vs[i] = gv[base + i]; }
    for (int i = tid; i < 4608; i += 256) kp[i] = 0.f;
    __syncthreads();
    for (int j = tid; j < 2048; j += 256) {
        int p = 2048 + j;
        float add = (j == 0) ? Dp[h] : 0.f;
        kp[p + (p >> 3)] = kerv[(size_t)h * LSEQ + j] + add;
    }
    __syncthreads();

    const int wid = tid >> 5, lane = tid & 31;
    const int strip = (wid < 4) ? wid : (11 - wid);
    const int l0 = strip * 256 + lane * 8;
    const int mmax = strip * 256 + 255;

    ull q2[4][4];
    #pragma unroll
    for (int d1 = 0; d1 < 4; d1++)
        #pragma unroll
        for (int r2 = 0; r2 < 4; r2++) {
            float2 qq = *(const float2*)&gq[base + (size_t)d1 * LSEQ + l0 + 2 * r2];
            q2[d1][r2] = pk2(qq.x, qq.y);
        }

    ull acc2[4][4];
    #pragma unroll
    for (int d = 0; d < 4; d++)
        #pragma unroll
        for (int r2 = 0; r2 < 4; r2++) acc2[d][r2] = 0ull;

    // sliding ker window: W0 = 2048 + l0 - 7 (≡ 1 mod 8); a(p) = p + (p>>3)
    int W0 = 2048 + l0 - 7;
    const float* Bf = kp + (W0 + (W0 >> 3));

    for (int mb = 0; mb <= mmax; mb += 8) {
        float w15[15];
        #pragma unroll
        for (int t = 0; t < 15; t++) w15[t] = Bf[t + (t >= 7 ? 1 : 0)];

        // ---- sub-chunk A: m = mb .. mb+3, window offset +4
        {
            float4 kf0 = *(const float4*)&ks[mb];
            float4 kf1 = *(const float4*)&ks[2048 + mb];
            float4 kf2 = *(const float4*)&ks[4096 + mb];
            float4 kf3 = *(const float4*)&ks[6144 + mb];
            float4 vf0 = *(const float4*)&vs[mb];
            float4 vf1 = *(const float4*)&vs[2048 + mb];
            float4 vf2 = *(const float4*)&vs[4096 + mb];
            float4 vf3 = *(const float4*)&vs[6144 + mb];
            float ka[4][4] = {{kf0.x,kf0.y,kf0.z,kf0.w},{kf1.x,kf1.y,kf1.z,kf1.w},
                              {kf2.x,kf2.y,kf2.z,kf2.w},{kf3.x,kf3.y,kf3.z,kf3.w}};
            float va[4][4] = {{vf0.x,vf0.y,vf0.z,vf0.w},{vf1.x,vf1.y,vf1.z,vf1.w},
                              {vf2.x,vf2.y,vf2.z,vf2.w},{vf3.x,vf3.y,vf3.z,vf3.w}};
            #pragma unroll
            for (int i = 0; i < 4; i++) {
                ull kk0 = pk2(ka[0][i], ka[0][i]), kk1 = pk2(ka[1][i], ka[1][i]);
                ull kk2 = pk2(ka[2][i], ka[2][i]), kk3 = pk2(ka[3][i], ka[3][i]);
                ull vv0 = pk2(va[0][i], va[0][i]), vv1 = pk2(va[1][i], va[1][i]);
                ull vv2 = pk2(va[2][i], va[2][i]), vv3 = pk2(va[3][i], va[3][i]);
                #pragma unroll
                for (int r2 = 0; r2 < 4; r2++) {
                    ull s = mul2(q2[0][r2], kk0);
                    s = fma2(q2[1][r2], kk1, s);
                    s = fma2(q2[2][r2], kk2, s);
                    s = fma2(q2[3][r2], kk3, s);
                    ull kerp = pk2(w15[2 * r2 - i + 7], w15[2 * r2 - i + 8]);
                    ull w = mul2(s, kerp);
                    acc2[0][r2] = fma2(w, vv0, acc2[0][r2]);
                    acc2[1][r2] = fma2(w, vv1, acc2[1][r2]);
                    acc2[2][r2] = fma2(w, vv2, acc2[2][r2]);
                    acc2[3][r2] = fma2(w, vv3, acc2[3][r2]);
                }
            }
        }
        // ---- sub-chunk B: m = mb+4 .. mb+7, window offset 0
        {
            float4 kf0 = *(const float4*)&ks[mb + 4];
            float4 kf1 = *(const float4*)&ks[2048 + mb + 4];
            float4 kf2 = *(const float4*)&ks[4096 + mb + 4];
            float4 kf3 = *(const float4*)&ks[6144 + mb + 4];
            float4 vf0 = *(const float4*)&vs[mb + 4];
            float4 vf1 = *(const float4*)&vs[2048 + mb + 4];
            float4 vf2 = *(const float4*)&vs[4096 + mb + 4];
            float4 vf3 = *(const float4*)&vs[6144 + mb + 4];
            float ka[4][4] = {{kf0.x,kf0.y,kf0.z,kf0.w},{kf1.x,kf1.y,kf1.z,kf1.w},
                              {kf2.x,kf2.y,kf2.z,kf2.w},{kf3.x,kf3.y,kf3.z,kf3.w}};
            float va[4][4] = {{vf0.x,vf0.y,vf0.z,vf0.w},{vf1.x,vf1.y,vf1.z,vf1.w},
                              {vf2.x,vf2.y,vf2.z,vf2.w},{vf3.x,vf3.y,vf3.z,vf3.w}};
            #pragma unroll
            for (int i = 0; i < 4; i++) {
                ull kk0 = pk2(ka[0][i], ka[0][i]), kk1 = pk2(ka[1][i], ka[1][i]);
                ull kk2 = pk2(ka[2][i], ka[2][i]), kk3 = pk2(ka[3][i], ka[3][i]);
                ull vv0 = pk2(va[0][i], va[0][i]), vv1 = pk2(va[1][i], va[1][i]);
                ull vv2 = pk2(va[2][i], va[2][i]), vv3 = pk2(va[3][i], va[3][i]);
                #pragma unroll
                for (int r2 = 0; r2 < 4; r2++) {
                    ull s = mul2(q2[0][r2], kk0);
                    s = fma2(q2[1][r2], kk1, s);
                    s = fma2(q2[2][r2], kk2, s);
                    s = fma2(q2[3][r2], kk3, s);
                    ull kerp = pk2(w15[2 * r2 - i + 3], w15[2 * r2 - i + 4]);
                    ull w = mul2(s, kerp);
                    acc2[0][r2] = fma2(w, vv0, acc2[0][r2]);
                    acc2[1][r2] = fma2(w, vv1, acc2[1][r2]);
                    acc2[2][r2] = fma2(w, vv2, acc2[2][r2]);
                    acc2[3][r2] = fma2(w, vv3, acc2[3][r2]);
                }
            }
        }
        Bf -= 9;
    }

    float acc[4][8];
    #pragma unroll
    for (int d = 0; d < 4; d++)
        #pragma unroll
        for (int r2 = 0; r2 < 4; r2++)
            upk2(acc2[d][r2], acc[d][2 * r2], acc[d][2 * r2 + 1]);

    #pragma unroll
    for (int d2 = 0; d2 < 4; d2++) {
        size_t orow = ((size_t)b * DM + (size_t)d2 * HH + h) * LSEQ + l0;
        #pragma unroll
        for (int r = 0; r < 8; r++) {
            float x = acc[d2][r];
            gy[orow + r] = 0.5f * x * (1.f + erff(x * 0.70710678118654752f));
        }
    }
}

// =============================================================================
extern "C" void kernel_launch(void* const* d_in, const int* in_sizes, int n_in,
                              void* d_out, int out_size)
{
    const float* u       = (const float*)d_in[0];
    const float* q_w     = (const float*)d_in[1];
    const float* q_b     = (const float*)d_in[2];
    const float* k_w     = (const float*)d_in[3];
    const float* k_b     = (const float*)d_in[4];
    const float* v_w     = (const float*)d_in[5];
    const float* v_b     = (const float*)d_in[6];
    const float* kkey_in = (const float*)d_in[7];
    const float* kv_in   = (const float*)d_in[8];
    const float* D_key   = (const float*)d_in[9];
    const float* Dh      = (const float*)d_in[10];
    const float* pw_w    = (const float*)d_in[11];
    const float* pw_b    = (const float*)d_in[12];
    float* out = (float*)d_out;

    float *kkey, *kvk, *q, *k, *v, *kc, *y, *bias;
    __nv_bfloat16 *wh, *wl, *xh, *xl;
    cudaGetSymbolAddress((void**)&kkey, g_kkey);
    cudaGetSymbolAddress((void**)&kvk,  g_kvker);
    cudaGetSymbolAddress((void**)&q,    g_q);
    cudaGetSymbolAddress((void**)&k,    g_k);
    cudaGetSymbolAddress((void**)&v,    g_v);
    cudaGetSymbolAddress((void**)&kc,   g_kc);
    cudaGetSymbolAddress((void**)&y,    g_y);
    cudaGetSymbolAddress((void**)&bias, g_bias);
    cudaGetSymbolAddress((void**)&wh,   g_wh);
    cudaGetSymbolAddress((void**)&wl,   g_wl);
    cudaGetSymbolAddress((void**)&xh,   g_xh);
    cudaGetSymbolAddress((void**)&xl,   g_xl);

    const int ATT_SMEM = (8192 + 8192 + 4608) * (int)sizeof(float);   // 83968
    const int KC_SMEM  = (2 * 4608 + 2 * 2048) * (int)sizeof(float);  // 53248
    cudaFuncSetAttribute(attn_kernel, cudaFuncAttributeMaxDynamicSharedMemorySize, ATT_SMEM);
    cudaFuncSetAttribute(keyconv_kernel, cudaFuncAttributeMaxDynamicSharedMemorySize, KC_SMEM);
    cudaFuncSetAttribute(mma_gemm, cudaFuncAttributeMaxDynamicSharedMemorySize, 3 * GSTG);

    const size_t WN = (size_t)DM * DM;

    // Launch order: keyconv is the 4th launch (= the one ncu captures).
    prep_all<<<17676, 256>>>(k_w, q_w, v_w, pw_w, wh, wl,
                             k_b, q_b, v_b, bias,
                             kkey_in, kv_in, kkey, kvk);                 // 1
    trans_split<<<dim3(LSEQ / 32, DM / 32, BB), 256>>>(u, xh, xl);       // 2
    mma_gemm<<<dim3(LSEQ / 128, 24, BB), 256, 3 * GSTG>>>(               // 3
        wh, wl, xh, xl, bias, 0, k, q, v);
    keyconv_kernel<<<dim3(DM / 2, BB), 256, KC_SMEM>>>(k, kkey, D_key, kc); // 4 (profiled)
    attn_kernel<<<dim3(HH, BB), 256, ATT_SMEM>>>(q, kc, v, kvk, Dh, y);  // 5
    trans_split<<<dim3(LSEQ / 32, DM / 32, BB), 256>>>(y, xh, xl);       // 6
    mma_gemm<<<dim3(LSEQ / 128, 8, BB), 256, 3 * GSTG>>>(                // 7
        wh + 3 * WN, wl + 3 * WN, xh, xl, pw_b, 0, out, out, out);
}

// round 15
// speedup vs baseline: 1.1575x; 1.0071x over previous
#include <cuda_runtime.h>
#include <cuda_bf16.h>
#include <stdint.h>
#include <math.h>

// Problem constants
#define DM   1024
#define LSEQ 2048
#define BB   4
#define HH   256   // heads
#define HD   4     // head dim

typedef unsigned long long ull;

// ---------------- scratch (device globals; no allocs allowed) ----------------
__device__ float g_kkey [DM * LSEQ];
__device__ float g_kvker[HH * LSEQ];
__device__ float g_q [BB * DM * LSEQ];
__device__ float g_k [BB * DM * LSEQ];
__device__ float g_v [BB * DM * LSEQ];
__device__ float g_kc[BB * DM * LSEQ];
__device__ float g_y [BB * DM * LSEQ];
__device__ float g_bias[3 * DM];                // packed k/q/v bias (K first)
// bf16 split operands for tensor-core GEMMs; weight order: K, Q, V, PW
__device__ __nv_bfloat16 g_wh[4][DM * DM];
__device__ __nv_bfloat16 g_wl[4][DM * DM];
__device__ __nv_bfloat16 g_xh[BB * LSEQ * DM];
__device__ __nv_bfloat16 g_xl[BB * LSEQ * DM];

// ======================= helpers (baseline ISA only) =========================
__device__ __forceinline__ uint32_t smem_u32(const void* p) {
    uint32_t a;
    asm("{ .reg .u64 t; cvta.to.shared.u64 t, %1; cvt.u32.u64 %0, t; }" : "=r"(a) : "l"(p));
    return a;
}
__device__ __forceinline__ void cp16(uint32_t dst, const void* src) {
    asm volatile("cp.async.cg.shared.global [%0], [%1], 16;" :: "r"(dst), "l"(src));
}
__device__ __forceinline__ void ldsm4(uint32_t* r, uint32_t addr) {
    asm volatile("ldmatrix.sync.aligned.m8n8.x4.shared.b16 {%0,%1,%2,%3}, [%4];"
        : "=r"(r[0]), "=r"(r[1]), "=r"(r[2]), "=r"(r[3]) : "r"(addr));
}
__device__ __forceinline__ void mma16816(float* d, const uint32_t* a, const uint32_t* b) {
    asm volatile("mma.sync.aligned.m16n8k16.row.col.f32.bf16.bf16.f32 "
        "{%0,%1,%2,%3}, {%4,%5,%6,%7}, {%8,%9}, {%0,%1,%2,%3};"
        : "+f"(d[0]), "+f"(d[1]), "+f"(d[2]), "+f"(d[3])
        : "r"(a[0]), "r"(a[1]), "r"(a[2]), "r"(a[3]), "r"(b[0]), "r"(b[1]));
}
// ---------------- packed fp32x2 (Blackwell) ----------------
__device__ __forceinline__ ull pk2(float a, float b) {
    ull d; asm("mov.b64 %0, {%1, %2};" : "=l"(d) : "f"(a), "f"(b)); return d;
}
__device__ __forceinline__ ull mul2(ull a, ull b) {
    ull d; asm("mul.rn.f32x2 %0, %1, %2;" : "=l"(d) : "l"(a), "l"(b)); return d;
}
__device__ __forceinline__ ull fma2(ull a, ull b, ull c) {
    ull d; asm("fma.rn.f32x2 %0, %1, %2, %3;" : "=l"(d) : "l"(a), "l"(b), "l"(c)); return d;
}
__device__ __forceinline__ void upk2(ull v, float& a, float& b) {
    asm("mov.b64 {%0, %1}, %2;" : "=f"(a), "=f"(b) : "l"(v));
}

// =============================================================================
// Merged prep kernel: wsplit [0,16384), pack_bias [16384,16396),
// build_kernels [16396,17676), trans_split(u) [17676,25868).
// =============================================================================
__global__ void prep_all(const float* __restrict__ w0, const float* __restrict__ w1,
                         const float* __restrict__ w2, const float* __restrict__ w3,
                         __nv_bfloat16* __restrict__ h, __nv_bfloat16* __restrict__ l,
                         const float* __restrict__ kb, const float* __restrict__ qb,
                         const float* __restrict__ vb, float* __restrict__ biasd,
                         const float* __restrict__ src_key, const float* __restrict__ src_val,
                         float* __restrict__ dst_key, float* __restrict__ dst_val,
                         const float* __restrict__ u,
                         __nv_bfloat16* __restrict__ xh, __nv_bfloat16* __restrict__ xl)
{
    __shared__ float sbuf[1056];   // union: red[256] / t[32][33]
    const int bid = blockIdx.x;
    const int tid = threadIdx.x;

    if (bid < 16384) {                 // ---- wsplit4
        const int m = bid >> 12;
        const float* w = (m == 0) ? w0 : (m == 1) ? w1 : (m == 2) ? w2 : w3;
        int i = (bid & 4095) * 256 + tid;
        size_t o = (size_t)m * (DM * DM) + i;
        float x = w[i];
        __nv_bfloat16 hh = __float2bfloat16(x);
        h[o] = hh;
        l[o] = __float2bfloat16(x - __bfloat162float(hh));
        return;
    }
    if (bid < 16396) {                 // ---- pack_bias (order K,Q,V)
        int i = (bid - 16384) * 256 + tid;
        biasd[i] = (i < DM) ? kb[i] : (i < 2 * DM) ? qb[i - DM] : vb[i - 2 * DM];
        return;
    }
    if (bid < 17676) {                 // ---- build_kernels
        const int cc  = bid - 16396;
        const int c   = (cc < DM) ? cc : cc - DM;
        const int nch = (cc < DM) ? DM : HH;
        const float* src = (cc < DM) ? src_key : src_val;
        float* dst       = (cc < DM) ? dst_key : dst_val;
        float vals[8];
        float ss = 0.f;
        #pragma unroll
        for (int r = 0; r < 8; r++) {
            int j = tid * 8 + r;
            int i, start;
            if      (j <   64) { i = 0; start = 0;    }
            else if (j <  128) { i = 1; start = 64;   }
            else if (j <  256) { i = 2; start = 128;  }
            else if (j <  512) { i = 3; start = 256;  }
            else if (j < 1024) { i = 4; start = 512;  }
            else               { i = 5; start = 1024; }
            int   s    = (i <= 1) ? 1 : (1 << (i - 1));
            float mult = (float)(1 << (5 - i));
            int   jj   = j - start;
            float pos  = ((float)jj + 0.5f) / (float)s - 0.5f;
            pos = fminf(fmaxf(pos, 0.f), 63.f);
            int   lo = (int)floorf(pos);
            int   hi = min(lo + 1, 63);
            float w  = pos - (float)lo;
            const float* row = src + ((size_t)i * nch + c) * 64;
            float v = (row[lo] * (1.f - w) + row[hi] * w) * mult;
            vals[r] = v;
            ss += v * v;
        }
        sbuf[tid] = ss;
        __syncthreads();
        for (int off = 128; off > 0; off >>= 1) {
            if (tid < off) sbuf[tid] += sbuf[tid + off];
            __syncthreads();
        }
        float inv = 1.f / sqrtf(sbuf[0]);
        #pragma unroll
        for (int r = 0; r < 8; r++)
            dst[(size_t)c * LSEQ + tid * 8 + r] = vals[r] * inv;
        return;
    }
    // ---- trans_split for u
    {
        const int tb = bid - 17676;
        const int l0 = (tb & 63) * 32;
        const int c0 = ((tb >> 6) & 31) * 32;
        const int b  = tb >> 11;
        float (*t)[33] = (float(*)[33])sbuf;
        const int tx = tid & 31, ty = tid >> 5;
        #pragma unroll
        for (int i = 0; i < 4; i++) {
            int c = c0 + ty + i * 8;
            t[ty + i * 8][tx] = u[((size_t)b * DM + c) * LSEQ + l0 + tx];
        }
        __syncthreads();
        #pragma unroll
        for (int i = 0; i < 4; i++) {
            int l = l0 + ty + i * 8;
            float x = t[tx][ty + i * 8];
            __nv_bfloat16 hh = __float2bfloat16(x);
            __nv_bfloat16 lo = __float2bfloat16(x - __bfloat162float(hh));
            size_t o = ((size_t)b * LSEQ + l) * DM + c0 + tx;
            xh[o] = hh; xl[o] = lo;
        }
    }
}

// =============================================================================
// standalone transpose (for y)
// =============================================================================
__global__ void __launch_bounds__(256)
trans_split(const float* __restrict__ in, __nv_bfloat16* __restrict__ oh,
            __nv_bfloat16* __restrict__ ol)
{
    __shared__ float t[32][33];
    const int tx = threadIdx.x & 31, ty = threadIdx.x >> 5;
    const int l0 = blockIdx.x * 32, c0 = blockIdx.y * 32, b = blockIdx.z;
    #pragma unroll
    for (int i = 0; i < 4; i++) {
        int c = c0 + ty + i * 8;
        t[ty + i * 8][tx] = in[((size_t)b * DM + c) * LSEQ + l0 + tx];
    }
    __syncthreads();
    #pragma unroll
    for (int i = 0; i < 4; i++) {
        int l = l0 + ty + i * 8;
        float x = t[tx][ty + i * 8];
        __nv_bfloat16 h = __float2bfloat16(x);
        __nv_bfloat16 lo = __float2bfloat16(x - __bfloat162float(h));
        size_t o = ((size_t)b * LSEQ + l) * DM + c0 + tx;
        oh[o] = h; ol[o] = lo;
    }
}

// =============================================================================
// mma.sync bf16 split GEMM — R12 config (measured qkv 375us).
// =============================================================================
#define GSTG 32768

__device__ __forceinline__ void g_load_stage(
    uint32_t sbuf, int stage, int tid,
    const char* Wh, const char* Wl, const char* Xh, const char* Xl,
    size_t wrow0, size_t xrow0)
{
    const int k0b = stage * 64;
    const int c16 = (tid & 3) * 16;
    const int r0  = tid >> 2;
    #pragma unroll
    for (int t = 0; t < 4; t++) {
        const char* base = (t == 0) ? Wh : (t == 1) ? Wl : (t == 2) ? Xh : Xl;
        const size_t rowbase = (t < 2) ? wrow0 : xrow0;
        #pragma unroll
        for (int j = 0; j < 2; j++) {
            int row = r0 + j * 64;
            int off = row * 64 + c16;
            int sw  = off ^ ((off >> 3) & 0x30);   // SW64
            cp16(sbuf + t * 8192 + (uint32_t)sw,
                 base + rowbase + (size_t)row * 2048 + k0b + c16);
        }
    }
    asm volatile("cp.async.commit_group;" ::: "memory");
}

__device__ __forceinline__ void g_compute_stage(
    uint32_t sbuf, int lane, int warpM, int warpN, float acc[2][8][4])
{
    const uint32_t Ah = sbuf, Al = sbuf + 8192;
    const uint32_t Bh = sbuf + 16384, Bl = sbuf + 24576;
    #pragma unroll
    for (int kk = 0; kk < 2; kk++) {
        uint32_t ah[2][4], al[2][4], bh[8][2], bl[8][2];
        #pragma unroll
        for (int mt = 0; mt < 2; mt++) {
            int m  = warpM * 32 + mt * 16 + (lane & 15);
            int kb = kk * 32 + (lane >> 4) * 16;
            int off = m * 64 + kb;
            int sw  = off ^ ((off >> 3) & 0x30);
            ldsm4(ah[mt], Ah + sw);
            ldsm4(al[mt], Al + sw);
        }
        #pragma unroll
        for (int nb2 = 0; nb2 < 4; nb2++) {
            int n  = warpN * 64 + nb2 * 16 + (lane >> 4) * 8 + (lane & 7);
            int kb = kk * 32 + ((lane >> 3) & 1) * 16;
            int off = n * 64 + kb;
            int sw  = off ^ ((off >> 3) & 0x30);
            uint32_t r[4];
            ldsm4(r, Bh + sw);
            bh[nb2 * 2][0] = r[0]; bh[nb2 * 2][1] = r[1];
            bh[nb2 * 2 + 1][0] = r[2]; bh[nb2 * 2 + 1][1] = r[3];
            ldsm4(r, Bl + sw);
            bl[nb2 * 2][0] = r[0]; bl[nb2 * 2][1] = r[1];
            bl[nb2 * 2 + 1][0] = r[2]; bl[nb2 * 2 + 1][1] = r[3];
        }
        #pragma unroll
        for (int mt = 0; mt < 2; mt++)
            #pragma unroll
            for (int nb = 0; nb < 8; nb++) {
                mma16816(acc[mt][nb], ah[mt], bh[nb]);
                mma16816(acc[mt][nb], ah[mt], bl[nb]);
                mma16816(acc[mt][nb], al[mt], bh[nb]);
            }
    }
}

__global__ void __launch_bounds__(256, 2)
mma_gemm(const __nv_bfloat16* __restrict__ Wh, const __nv_bfloat16* __restrict__ Wl,
         const __nv_bfloat16* __restrict__ Xh, const __nv_bfloat16* __restrict__ Xl,
         const float* __restrict__ bias, int mbase,
         float* __restrict__ Y0, float* __restrict__ Y1, float* __restrict__ Y2)
{
    extern __shared__ char smem[];
    const uint32_t sb = smem_u32(smem);
    const int tid = threadIdx.x, wid = tid >> 5, lane = tid & 31;
    const int warpM = wid & 3, warpN = wid >> 2;
    const int n0 = blockIdx.x * 128, m0 = mbase + blockIdx.y * 128, b = blockIdx.z;
    const size_t wrow0 = (size_t)m0 * 2048;
    const size_t xrow0 = ((size_t)b * LSEQ + n0) * 2048;
    const char* cWh = (const char*)Wh; const char* cWl = (const char*)Wl;
    const char* cXh = (const char*)Xh; const char* cXl = (const char*)Xl;

    float acc[2][8][4];
    #pragma unroll
    for (int mt = 0; mt < 2; mt++)
        #pragma unroll
        for (int nb = 0; nb < 8; nb++)
            #pragma unroll
            for (int j = 0; j < 4; j++) acc[mt][nb][j] = 0.f;

    g_load_stage(sb,            0, tid, cWh, cWl, cXh, cXl, wrow0, xrow0);
    g_load_stage(sb + GSTG,     1, tid, cWh, cWl, cXh, cXl, wrow0, xrow0);
    g_load_stage(sb + 2 * GSTG, 2, tid, cWh, cWl, cXh, cXl, wrow0, xrow0);

    int slot = 0;
    for (int st = 0; st < 32; st++) {
        if (st <= 29)      asm volatile("cp.async.wait_group 2;" ::: "memory");
        else if (st == 30) asm volatile("cp.async.wait_group 1;" ::: "memory");
        else               asm volatile("cp.async.wait_group 0;" ::: "memory");
        __syncthreads();
        g_compute_stage(sb + slot * GSTG, lane, warpM, warpN, acc);
        __syncthreads();
        if (st + 3 < 32)
            g_load_stage(sb + slot * GSTG, st + 3, tid, cWh, cWl, cXh, cXl, wrow0, xrow0);
        slot = (slot == 2) ? 0 : slot + 1;
    }

    const int mat = m0 >> 10;
    float* Y = (mat == 0) ? Y0 : (mat == 1) ? Y1 : Y2;
    const int rq = lane >> 2;
    const int cq = (lane & 3) * 2;
    #pragma unroll
    for (int mt = 0; mt < 2; mt++) {
        const int rs = m0 + warpM * 32 + mt * 16 + rq;
        const int row = rs & 1023;
        const float b0 = bias[rs], b1 = bias[rs + 8];
        const size_t y0 = ((size_t)b * DM + row) * LSEQ;
        #pragma unroll
        for (int nb = 0; nb < 8; nb++) {
            const int col = n0 + warpN * 64 + nb * 8 + cq;
            float2 v0, v1;
            v0.x = acc[mt][nb][0] + b0; v0.y = acc[mt][nb][1] + b0;
            v1.x = acc[mt][nb][2] + b1; v1.y = acc[mt][nb][3] + b1;
            *(float2*)&Y[y0 + col] = v0;
            *(float2*)&Y[y0 + 8 * LSEQ + col] = v1;
        }
    }
}

// =============================================================================
// Kernel C: causal long conv (dkey folded).  Dup-pair layouts kill all pk2:
//  - K pre-packed (k,k) ull pairs: broadcast LDS.64 (j0 warp-uniform).
//  - x dup array addr(p)=2p+((p>>4)<<1): pair (x[p],x[p+1]) = one LDS.64.
//    Lane stride 34 floats = 17 8B-units (odd) -> conflict-free.
//    W0 = 2048+l0-15 (== 1 mod 16) -> offsets 2t+2*[t>=15] compile-time,
//    base slides -34 floats per 16-j chunk.  Accumulation order unchanged.
// smem: xd0/xd1 8704 fl + kq0/kq1 4096 fl = 25600 fl = 102400 B.
// =============================================================================
__global__ void __launch_bounds__(256)
keyconv_kernel(const float* __restrict__ kk, const float* __restrict__ kker,
               const float* __restrict__ dkey, float* __restrict__ out)
{
    extern __shared__ float dsm[];
    float* xd0 = dsm;                 // 8704
    float* xd1 = dsm + 8704;          // 8704
    ull*   kq0 = (ull*)(dsm + 17408); // 2048 pairs
    ull*   kq1 = (ull*)(dsm + 21504); // 2048 pairs
    const int c0 = blockIdx.x * 2, b = blockIdx.y;
    const int tid = threadIdx.x;
    const size_t rb0 = ((size_t)b * DM + c0) * LSEQ;
    const size_t rb1 = rb0 + LSEQ;

    for (int i = tid; i < 8704; i += 256) { xd0[i] = 0.f; xd1[i] = 0.f; }
    __syncthreads();
    for (int i = tid; i < 2048; i += 256) {
        float add0 = (i == 0) ? dkey[c0] : 0.f;
        float add1 = (i == 0) ? dkey[c0 + 1] : 0.f;
        float k0v = kker[(size_t)c0 * LSEQ + i] + add0;
        float k1v = kker[(size_t)(c0 + 1) * LSEQ + i] + add1;
        kq0[i] = pk2(k0v, k0v);
        kq1[i] = pk2(k1v, k1v);
        int p  = 2048 + i;
        int a0 = 2 * p + ((p >> 4) << 1);
        int am = 2 * (p - 1) + (((p - 1) >> 4) << 1) + 1;
        float x0 = kk[rb0 + i];
        float x1 = kk[rb1 + i];
        xd0[a0] = x0; xd0[am] = x0;
        xd1[a0] = x1; xd1[am] = x1;
    }
    __syncthreads();

    const int wid = tid >> 5, lane = tid & 31;
    const int ch = (wid < 4) ? 0 : 1;
    const int strip = (wid < 4) ? wid : (7 - wid);
    const float* Xd = ch ? xd1 : xd0;
    const ull*   Kq = ch ? kq1 : kq0;
    const size_t rowbase = ch ? rb1 : rb0;
    const int l0 = strip * 512 + lane * 16;
    const int jmax = strip * 512 + 511;

    ull acc2[8];
    #pragma unroll
    for (int r2 = 0; r2 < 8; r2++) acc2[r2] = 0ull;

    int W0 = 2048 + l0 - 15;
    const float* Bd = Xd + (2 * W0 + ((W0 >> 4) << 1));

    for (int j0 = 0; j0 <= jmax; j0 += 16) {
        ull xv2[30];
        #pragma unroll
        for (int t = 0; t < 30; t++)
            xv2[t] = *(const ull*)(Bd + 2 * t + ((t >= 15) ? 2 : 0));

        // sub-chunk A: j in [j0, j0+7], window offset +15
        {
            ull kr2[8];
            #pragma unroll
            for (int s = 0; s < 8; s++) kr2[s] = Kq[j0 + s];
            #pragma unroll
            for (int r2 = 0; r2 < 8; r2++)
                #pragma unroll
                for (int s = 0; s < 8; s++)
                    acc2[r2] = fma2(kr2[s], xv2[2 * r2 - s + 15], acc2[r2]);
        }
        // sub-chunk B: j in [j0+8, j0+15], window offset +7
        {
            ull kr2[8];
            #pragma unroll
            for (int s = 0; s < 8; s++) kr2[s] = Kq[j0 + 8 + s];
            #pragma unroll
            for (int r2 = 0; r2 < 8; r2++)
                #pragma unroll
                for (int s = 0; s < 8; s++)
                    acc2[r2] = fma2(kr2[s], xv2[2 * r2 - s + 7], acc2[r2]);
        }
        Bd -= 34;
    }
    #pragma unroll
    for (int r2 = 0; r2 < 8; r2++) {
        float a0, a1;
        upk2(acc2[r2], a0, a1);
        out[rowbase + l0 + 2 * r2]     = a0;
        out[rowbase + l0 + 2 * r2 + 1] = a1;
    }
}

// =============================================================================
// Kernel D: kernel-weighted linear attention (R14 body, unchanged; now the
// 4th launch => profiled).
// =============================================================================
__global__ void __launch_bounds__(256)
attn_kernel(const float* __restrict__ gq, const float* __restrict__ gk,
            const float* __restrict__ gv, const float* __restrict__ kerv,
            const float* __restrict__ Dp, float* __restrict__ gy)
{
    extern __shared__ float sm[];
    float* ks = sm;
    float* vs = sm + 8192;
    float* kp = sm + 16384;
    const int h = blockIdx.x, b = blockIdx.y;
    const int tid = threadIdx.x;
    const size_t base = ((size_t)b * DM + (size_t)h * HD) * LSEQ;

    for (int i = tid; i < 8192; i += 256) { ks[i] = gk[base + i]; vs[i] = gv[base + i]; }
    for (int i = tid; i < 4608; i += 256) kp[i] = 0.f;
    __syncthreads();
    for (int j = tid; j < 2048; j += 256) {
        int p = 2048 + j;
        float add = (j == 0) ? Dp[h] : 0.f;
        kp[p + (p >> 3)] = kerv[(size_t)h * LSEQ + j] + add;
    }
    __syncthreads();

    const int wid = tid >> 5, lane = tid & 31;
    const int strip = (wid < 4) ? wid : (11 - wid);
    const int l0 = strip * 256 + lane * 8;
    const int mmax = strip * 256 + 255;

    ull q2[4][4];
    #pragma unroll
    for (int d1 = 0; d1 < 4; d1++)
        #pragma unroll
        for (int r2 = 0; r2 < 4; r2++) {
            float2 qq = *(const float2*)&gq[base + (size_t)d1 * LSEQ + l0 + 2 * r2];
            q2[d1][r2] = pk2(qq.x, qq.y);
        }

    ull acc2[4][4];
    #pragma unroll
    for (int d = 0; d < 4; d++)
        #pragma unroll
        for (int r2 = 0; r2 < 4; r2++) acc2[d][r2] = 0ull;

    int W0 = 2048 + l0 - 7;
    const float* Bf = kp + (W0 + (W0 >> 3));

    for (int mb = 0; mb <= mmax; mb += 8) {
        float w15[15];
        #pragma unroll
        for (int t = 0; t < 15; t++) w15[t] = Bf[t + (t >= 7 ? 1 : 0)];

        {
            float4 kf0 = *(const float4*)&ks[mb];
            float4 kf1 = *(const float4*)&ks[2048 + mb];
            float4 kf2 = *(const float4*)&ks[4096 + mb];
            float4 kf3 = *(const float4*)&ks[6144 + mb];
            float4 vf0 = *(const float4*)&vs[mb];
            float4 vf1 = *(const float4*)&vs[2048 + mb];
            float4 vf2 = *(const float4*)&vs[4096 + mb];
            float4 vf3 = *(const float4*)&vs[6144 + mb];
            float ka[4][4] = {{kf0.x,kf0.y,kf0.z,kf0.w},{kf1.x,kf1.y,kf1.z,kf1.w},
                              {kf2.x,kf2.y,kf2.z,kf2.w},{kf3.x,kf3.y,kf3.z,kf3.w}};
            float va[4][4] = {{vf0.x,vf0.y,vf0.z,vf0.w},{vf1.x,vf1.y,vf1.z,vf1.w},
                              {vf2.x,vf2.y,vf2.z,vf2.w},{vf3.x,vf3.y,vf3.z,vf3.w}};
            #pragma unroll
            for (int i = 0; i < 4; i++) {
                ull kk0 = pk2(ka[0][i], ka[0][i]), kk1 = pk2(ka[1][i], ka[1][i]);
                ull kk2 = pk2(ka[2][i], ka[2][i]), kk3 = pk2(ka[3][i], ka[3][i]);
                ull vv0 = pk2(va[0][i], va[0][i]), vv1 = pk2(va[1][i], va[1][i]);
                ull vv2 = pk2(va[2][i], va[2][i]), vv3 = pk2(va[3][i], va[3][i]);
                #pragma unroll
                for (int r2 = 0; r2 < 4; r2++) {
                    ull s = mul2(q2[0][r2], kk0);
                    s = fma2(q2[1][r2], kk1, s);
                    s = fma2(q2[2][r2], kk2, s);
                    s = fma2(q2[3][r2], kk3, s);
                    ull kerp = pk2(w15[2 * r2 - i + 7], w15[2 * r2 - i + 8]);
                    ull w = mul2(s, kerp);
                    acc2[0][r2] = fma2(w, vv0, acc2[0][r2]);
                    acc2[1][r2] = fma2(w, vv1, acc2[1][r2]);
                    acc2[2][r2] = fma2(w, vv2, acc2[2][r2]);
                    acc2[3][r2] = fma2(w, vv3, acc2[3][r2]);
                }
            }
        }
        {
            float4 kf0 = *(const float4*)&ks[mb + 4];
            float4 kf1 = *(const float4*)&ks[2048 + mb + 4];
            float4 kf2 = *(const float4*)&ks[4096 + mb + 4];
            float4 kf3 = *(const float4*)&ks[6144 + mb + 4];
            float4 vf0 = *(const float4*)&vs[mb + 4];
            float4 vf1 = *(const float4*)&vs[2048 + mb + 4];
            float4 vf2 = *(const float4*)&vs[4096 + mb + 4];
            float4 vf3 = *(const float4*)&vs[6144 + mb + 4];
            float ka[4][4] = {{kf0.x,kf0.y,kf0.z,kf0.w},{kf1.x,kf1.y,kf1.z,kf1.w},
                              {kf2.x,kf2.y,kf2.z,kf2.w},{kf3.x,kf3.y,kf3.z,kf3.w}};
            float va[4][4] = {{vf0.x,vf0.y,vf0.z,vf0.w},{vf1.x,vf1.y,vf1.z,vf1.w},
                              {vf2.x,vf2.y,vf2.z,vf2.w},{vf3.x,vf3.y,vf3.z,vf3.w}};
            #pragma unroll
            for (int i = 0; i < 4; i++) {
                ull kk0 = pk2(ka[0][i], ka[0][i]), kk1 = pk2(ka[1][i], ka[1][i]);
                ull kk2 = pk2(ka[2][i], ka[2][i]), kk3 = pk2(ka[3][i], ka[3][i]);
                ull vv0 = pk2(va[0][i], va[0][i]), vv1 = pk2(va[1][i], va[1][i]);
                ull vv2 = pk2(va[2][i], va[2][i]), vv3 = pk2(va[3][i], va[3][i]);
                #pragma unroll
                for (int r2 = 0; r2 < 4; r2++) {
                    ull s = mul2(q2[0][r2], kk0);
                    s = fma2(q2[1][r2], kk1, s);
                    s = fma2(q2[2][r2], kk2, s);
                    s = fma2(q2[3][r2], kk3, s);
                    ull kerp = pk2(w15[2 * r2 - i + 3], w15[2 * r2 - i + 4]);
                    ull w = mul2(s, kerp);
                    acc2[0][r2] = fma2(w, vv0, acc2[0][r2]);
                    acc2[1][r2] = fma2(w, vv1, acc2[1][r2]);
                    acc2[2][r2] = fma2(w, vv2, acc2[2][r2]);
                    acc2[3][r2] = fma2(w, vv3, acc2[3][r2]);
                }
            }
        }
        Bf -= 9;
    }

    float acc[4][8];
    #pragma unroll
    for (int d = 0; d < 4; d++)
        #pragma unroll
        for (int r2 = 0; r2 < 4; r2++)
            upk2(acc2[d][r2], acc[d][2 * r2], acc[d][2 * r2 + 1]);

    #pragma unroll
    for (int d2 = 0; d2 < 4; d2++) {
        size_t orow = ((size_t)b * DM + (size_t)d2 * HH + h) * LSEQ + l0;
        #pragma unroll
        for (int r = 0; r < 8; r++) {
            float x = acc[d2][r];
            gy[orow + r] = 0.5f * x * (1.f + erff(x * 0.70710678118654752f));
        }
    }
}

// =============================================================================
extern "C" void kernel_launch(void* const* d_in, const int* in_sizes, int n_in,
                              void* d_out, int out_size)
{
    const float* u       = (const float*)d_in[0];
    const float* q_w     = (const float*)d_in[1];
    const float* q_b     = (const float*)d_in[2];
    const float* k_w     = (const float*)d_in[3];
    const float* k_b     = (const float*)d_in[4];
    const float* v_w     = (const float*)d_in[5];
    const float* v_b     = (const float*)d_in[6];
    const float* kkey_in = (const float*)d_in[7];
    const float* kv_in   = (const float*)d_in[8];
    const float* D_key   = (const float*)d_in[9];
    const float* Dh      = (const float*)d_in[10];
    const float* pw_w    = (const float*)d_in[11];
    const float* pw_b    = (const float*)d_in[12];
    float* out = (float*)d_out;

    float *kkey, *kvk, *q, *k, *v, *kc, *y, *bias;
    __nv_bfloat16 *wh, *wl, *xh, *xl;
    cudaGetSymbolAddress((void**)&kkey, g_kkey);
    cudaGetSymbolAddress((void**)&kvk,  g_kvker);
    cudaGetSymbolAddress((void**)&q,    g_q);
    cudaGetSymbolAddress((void**)&k,    g_k);
    cudaGetSymbolAddress((void**)&v,    g_v);
    cudaGetSymbolAddress((void**)&kc,   g_kc);
    cudaGetSymbolAddress((void**)&y,    g_y);
    cudaGetSymbolAddress((void**)&bias, g_bias);
    cudaGetSymbolAddress((void**)&wh,   g_wh);
    cudaGetSymbolAddress((void**)&wl,   g_wl);
    cudaGetSymbolAddress((void**)&xh,   g_xh);
    cudaGetSymbolAddress((void**)&xl,   g_xl);

    const int ATT_SMEM = (8192 + 8192 + 4608) * (int)sizeof(float);   // 83968
    const int KC_SMEM  = 25600 * (int)sizeof(float);                  // 102400
    cudaFuncSetAttribute(attn_kernel, cudaFuncAttributeMaxDynamicSharedMemorySize, ATT_SMEM);
    cudaFuncSetAttribute(keyconv_kernel, cudaFuncAttributeMaxDynamicSharedMemorySize, KC_SMEM);
    cudaFuncSetAttribute(mma_gemm, cudaFuncAttributeMaxDynamicSharedMemorySize, 3 * GSTG);

    const size_t WN = (size_t)DM * DM;

    // Launch order: attn is the 4th launch (= the one ncu captures).
    prep_all<<<25868, 256>>>(k_w, q_w, v_w, pw_w, wh, wl,
                             k_b, q_b, v_b, bias,
                             kkey_in, kv_in, kkey, kvk,
                             u, xh, xl);                                 // 1
    mma_gemm<<<dim3(LSEQ / 128, 24, BB), 256, 3 * GSTG>>>(               // 2
        wh, wl, xh, xl, bias, 0, k, q, v);
    keyconv_kernel<<<dim3(DM / 2, BB), 256, KC_SMEM>>>(k, kkey, D_key, kc); // 3
    attn_kernel<<<dim3(HH, BB), 256, ATT_SMEM>>>(q, kc, v, kvk, Dh, y);  // 4 (profiled)
    trans_split<<<dim3(LSEQ / 32, DM / 32, BB), 256>>>(y, xh, xl);       // 5
    mma_gemm<<<dim3(LSEQ / 128, 8, BB), 256, 3 * GSTG>>>(                // 6
        wh + 3 * WN, wl + 3 * WN, xh, xl, pw_b, 0, out, out, out);
}

// round 17
// speedup vs baseline: 1.2265x; 1.0597x over previous
#include <cuda_runtime.h>
#include <cuda_bf16.h>
#include <stdint.h>
#include <math.h>

// Problem constants
#define DM   1024
#define LSEQ 2048
#define BB   4
#define HH   256   // heads
#define HD   4     // head dim

typedef unsigned long long ull;

// ---------------- scratch (device globals; no allocs allowed) ----------------
__device__ float g_kkey [DM * LSEQ];
__device__ float g_kvker[HH * LSEQ];
__device__ float g_q [BB * DM * LSEQ];
__device__ float g_k [BB * DM * LSEQ];
__device__ float g_v [BB * DM * LSEQ];
__device__ float g_kc[BB * DM * LSEQ];
__device__ float g_y [BB * DM * LSEQ];
__device__ float g_bias[3 * DM];                // packed k/q/v bias (K first)
// bf16 split operands for tensor-core GEMMs; weight order: K, Q, V, PW
__device__ __nv_bfloat16 g_wh[4][DM * DM];
__device__ __nv_bfloat16 g_wl[4][DM * DM];
__device__ __nv_bfloat16 g_xh[BB * LSEQ * DM];
__device__ __nv_bfloat16 g_xl[BB * LSEQ * DM];

// ======================= helpers (baseline ISA only) =========================
__device__ __forceinline__ uint32_t smem_u32(const void* p) {
    uint32_t a;
    asm("{ .reg .u64 t; cvta.to.shared.u64 t, %1; cvt.u32.u64 %0, t; }" : "=r"(a) : "l"(p));
    return a;
}
__device__ __forceinline__ void cp16(uint32_t dst, const void* src) {
    asm volatile("cp.async.cg.shared.global [%0], [%1], 16;" :: "r"(dst), "l"(src));
}
__device__ __forceinline__ void ldsm4(uint32_t* r, uint32_t addr) {
    asm volatile("ldmatrix.sync.aligned.m8n8.x4.shared.b16 {%0,%1,%2,%3}, [%4];"
        : "=r"(r[0]), "=r"(r[1]), "=r"(r[2]), "=r"(r[3]) : "r"(addr));
}
__device__ __forceinline__ void mma16816(float* d, const uint32_t* a, const uint32_t* b) {
    asm volatile("mma.sync.aligned.m16n8k16.row.col.f32.bf16.bf16.f32 "
        "{%0,%1,%2,%3}, {%4,%5,%6,%7}, {%8,%9}, {%0,%1,%2,%3};"
        : "+f"(d[0]), "+f"(d[1]), "+f"(d[2]), "+f"(d[3])
        : "r"(a[0]), "r"(a[1]), "r"(a[2]), "r"(a[3]), "r"(b[0]), "r"(b[1]));
}
// ---------------- packed fp32x2 (Blackwell) ----------------
__device__ __forceinline__ ull pk2(float a, float b) {
    ull d; asm("mov.b64 %0, {%1, %2};" : "=l"(d) : "f"(a), "f"(b)); return d;
}
__device__ __forceinline__ ull mul2(ull a, ull b) {
    ull d; asm("mul.rn.f32x2 %0, %1, %2;" : "=l"(d) : "l"(a), "l"(b)); return d;
}
__device__ __forceinline__ ull fma2(ull a, ull b, ull c) {
    ull d; asm("fma.rn.f32x2 %0, %1, %2, %3;" : "=l"(d) : "l"(a), "l"(b), "l"(c)); return d;
}
__device__ __forceinline__ void upk2(ull v, float& a, float& b) {
    asm("mov.b64 {%0, %1}, %2;" : "=f"(a), "=f"(b) : "l"(v));
}

// =============================================================================
// Merged prep kernel: wsplit [0,16384), pack_bias [16384,16396),
// build_kernels [16396,17676), trans_split(u) [17676,25868).
// =============================================================================
__global__ void prep_all(const float* __restrict__ w0, const float* __restrict__ w1,
                         const float* __restrict__ w2, const float* __restrict__ w3,
                         __nv_bfloat16* __restrict__ h, __nv_bfloat16* __restrict__ l,
                         const float* __restrict__ kb, const float* __restrict__ qb,
                         const float* __restrict__ vb, float* __restrict__ biasd,
                         const float* __restrict__ src_key, const float* __restrict__ src_val,
                         float* __restrict__ dst_key, float* __restrict__ dst_val,
                         const float* __restrict__ u,
                         __nv_bfloat16* __restrict__ xh, __nv_bfloat16* __restrict__ xl)
{
    __shared__ float sbuf[1056];
    const int bid = blockIdx.x;
    const int tid = threadIdx.x;

    if (bid < 16384) {
        const int m = bid >> 12;
        const float* w = (m == 0) ? w0 : (m == 1) ? w1 : (m == 2) ? w2 : w3;
        int i = (bid & 4095) * 256 + tid;
        size_t o = (size_t)m * (DM * DM) + i;
        float x = w[i];
        __nv_bfloat16 hh = __float2bfloat16(x);
        h[o] = hh;
        l[o] = __float2bfloat16(x - __bfloat162float(hh));
        return;
    }
    if (bid < 16396) {
        int i = (bid - 16384) * 256 + tid;
        biasd[i] = (i < DM) ? kb[i] : (i < 2 * DM) ? qb[i - DM] : vb[i - 2 * DM];
        return;
    }
    if (bid < 17676) {
        const int cc  = bid - 16396;
        const int c   = (cc < DM) ? cc : cc - DM;
        const int nch = (cc < DM) ? DM : HH;
        const float* src = (cc < DM) ? src_key : src_val;
        float* dst       = (cc < DM) ? dst_key : dst_val;
        float vals[8];
        float ss = 0.f;
        #pragma unroll
        for (int r = 0; r < 8; r++) {
            int j = tid * 8 + r;
            int i, start;
            if      (j <   64) { i = 0; start = 0;    }
            else if (j <  128) { i = 1; start = 64;   }
            else if (j <  256) { i = 2; start = 128;  }
            else if (j <  512) { i = 3; start = 256;  }
            else if (j < 1024) { i = 4; start = 512;  }
            else               { i = 5; start = 1024; }
            int   s    = (i <= 1) ? 1 : (1 << (i - 1));
            float mult = (float)(1 << (5 - i));
            int   jj   = j - start;
            float pos  = ((float)jj + 0.5f) / (float)s - 0.5f;
            pos = fminf(fmaxf(pos, 0.f), 63.f);
            int   lo = (int)floorf(pos);
            int   hi = min(lo + 1, 63);
            float w  = pos - (float)lo;
            const float* row = src + ((size_t)i * nch + c) * 64;
            float v = (row[lo] * (1.f - w) + row[hi] * w) * mult;
            vals[r] = v;
            ss += v * v;
        }
        sbuf[tid] = ss;
        __syncthreads();
        for (int off = 128; off > 0; off >>= 1) {
            if (tid < off) sbuf[tid] += sbuf[tid + off];
            __syncthreads();
        }
        float inv = 1.f / sqrtf(sbuf[0]);
        #pragma unroll
        for (int r = 0; r < 8; r++)
            dst[(size_t)c * LSEQ + tid * 8 + r] = vals[r] * inv;
        return;
    }
    {
        const int tb = bid - 17676;
        const int l0 = (tb & 63) * 32;
        const int c0 = ((tb >> 6) & 31) * 32;
        const int b  = tb >> 11;
        float (*t)[33] = (float(*)[33])sbuf;
        const int tx = tid & 31, ty = tid >> 5;
        #pragma unroll
        for (int i = 0; i < 4; i++) {
            int c = c0 + ty + i * 8;
            t[ty + i * 8][tx] = u[((size_t)b * DM + c) * LSEQ + l0 + tx];
        }
        __syncthreads();
        #pragma unroll
        for (int i = 0; i < 4; i++) {
            int l = l0 + ty + i * 8;
            float x = t[tx][ty + i * 8];
            __nv_bfloat16 hh = __float2bfloat16(x);
            __nv_bfloat16 lo = __float2bfloat16(x - __bfloat162float(hh));
            size_t o = ((size_t)b * LSEQ + l) * DM + c0 + tx;
            xh[o] = hh; xl[o] = lo;
        }
    }
}

// =============================================================================
// standalone transpose (for y)
// =============================================================================
__global__ void __launch_bounds__(256)
trans_split(const float* __restrict__ in, __nv_bfloat16* __restrict__ oh,
            __nv_bfloat16* __restrict__ ol)
{
    __shared__ float t[32][33];
    const int tx = threadIdx.x & 31, ty = threadIdx.x >> 5;
    const int l0 = blockIdx.x * 32, c0 = blockIdx.y * 32, b = blockIdx.z;
    #pragma unroll
    for (int i = 0; i < 4; i++) {
        int c = c0 + ty + i * 8;
        t[ty + i * 8][tx] = in[((size_t)b * DM + c) * LSEQ + l0 + tx];
    }
    __syncthreads();
    #pragma unroll
    for (int i = 0; i < 4; i++) {
        int l = l0 + ty + i * 8;
        float x = t[tx][ty + i * 8];
        __nv_bfloat16 h = __float2bfloat16(x);
        __nv_bfloat16 lo = __float2bfloat16(x - __bfloat162float(h));
        size_t o = ((size_t)b * LSEQ + l) * DM + c0 + tx;
        oh[o] = h; ol[o] = lo;
    }
}

// =============================================================================
// mma.sync bf16 split GEMM — R12 config (measured qkv 375us).
// =============================================================================
#define GSTG 32768

__device__ __forceinline__ void g_load_stage(
    uint32_t sbuf, int stage, int tid,
    const char* Wh, const char* Wl, const char* Xh, const char* Xl,
    size_t wrow0, size_t xrow0)
{
    const int k0b = stage * 64;
    const int c16 = (tid & 3) * 16;
    const int r0  = tid >> 2;
    #pragma unroll
    for (int t = 0; t < 4; t++) {
        const char* base = (t == 0) ? Wh : (t == 1) ? Wl : (t == 2) ? Xh : Xl;
        const size_t rowbase = (t < 2) ? wrow0 : xrow0;
        #pragma unroll
        for (int j = 0; j < 2; j++) {
            int row = r0 + j * 64;
            int off = row * 64 + c16;
            int sw  = off ^ ((off >> 3) & 0x30);   // SW64
            cp16(sbuf + t * 8192 + (uint32_t)sw,
                 base + rowbase + (size_t)row * 2048 + k0b + c16);
        }
    }
    asm volatile("cp.async.commit_group;" ::: "memory");
}

__device__ __forceinline__ void g_compute_stage(
    uint32_t sbuf, int lane, int warpM, int warpN, float acc[2][8][4])
{
    const uint32_t Ah = sbuf, Al = sbuf + 8192;
    const uint32_t Bh = sbuf + 16384, Bl = sbuf + 24576;
    #pragma unroll
    for (int kk = 0; kk < 2; kk++) {
        uint32_t ah[2][4], al[2][4], bh[8][2], bl[8][2];
        #pragma unroll
        for (int mt = 0; mt < 2; mt++) {
            int m  = warpM * 32 + mt * 16 + (lane & 15);
            int kb = kk * 32 + (lane >> 4) * 16;
            int off = m * 64 + kb;
            int sw  = off ^ ((off >> 3) & 0x30);
            ldsm4(ah[mt], Ah + sw);
            ldsm4(al[mt], Al + sw);
        }
        #pragma unroll
        for (int nb2 = 0; nb2 < 4; nb2++) {
            int n  = warpN * 64 + nb2 * 16 + (lane >> 4) * 8 + (lane & 7);
            int kb = kk * 32 + ((lane >> 3) & 1) * 16;
            int off = n * 64 + kb;
            int sw  = off ^ ((off >> 3) & 0x30);
            uint32_t r[4];
            ldsm4(r, Bh + sw);
            bh[nb2 * 2][0] = r[0]; bh[nb2 * 2][1] = r[1];
            bh[nb2 * 2 + 1][0] = r[2]; bh[nb2 * 2 + 1][1] = r[3];
            ldsm4(r, Bl + sw);
            bl[nb2 * 2][0] = r[0]; bl[nb2 * 2][1] = r[1];
            bl[nb2 * 2 + 1][0] = r[2]; bl[nb2 * 2 + 1][1] = r[3];
        }
        #pragma unroll
        for (int mt = 0; mt < 2; mt++)
            #pragma unroll
            for (int nb = 0; nb < 8; nb++) {
                mma16816(acc[mt][nb], ah[mt], bh[nb]);
                mma16816(acc[mt][nb], ah[mt], bl[nb]);
                mma16816(acc[mt][nb], al[mt], bh[nb]);
            }
    }
}

__global__ void __launch_bounds__(256, 2)
mma_gemm(const __nv_bfloat16* __restrict__ Wh, const __nv_bfloat16* __restrict__ Wl,
         const __nv_bfloat16* __restrict__ Xh, const __nv_bfloat16* __restrict__ Xl,
         const float* __restrict__ bias, int mbase,
         float* __restrict__ Y0, float* __restrict__ Y1, float* __restrict__ Y2)
{
    extern __shared__ char smem[];
    const uint32_t sb = smem_u32(smem);
    const int tid = threadIdx.x, wid = tid >> 5, lane = tid & 31;
    const int warpM = wid & 3, warpN = wid >> 2;
    const int n0 = blockIdx.x * 128, m0 = mbase + blockIdx.y * 128, b = blockIdx.z;
    const size_t wrow0 = (size_t)m0 * 2048;
    const size_t xrow0 = ((size_t)b * LSEQ + n0) * 2048;
    const char* cWh = (const char*)Wh; const char* cWl = (const char*)Wl;
    const char* cXh = (const char*)Xh; const char* cXl = (const char*)Xl;

    float acc[2][8][4];
    #pragma unroll
    for (int mt = 0; mt < 2; mt++)
        #pragma unroll
        for (int nb = 0; nb < 8; nb++)
            #pragma unroll
            for (int j = 0; j < 4; j++) acc[mt][nb][j] = 0.f;

    g_load_stage(sb,            0, tid, cWh, cWl, cXh, cXl, wrow0, xrow0);
    g_load_stage(sb + GSTG,     1, tid, cWh, cWl, cXh, cXl, wrow0, xrow0);
    g_load_stage(sb + 2 * GSTG, 2, tid, cWh, cWl, cXh, cXl, wrow0, xrow0);

    int slot = 0;
    for (int st = 0; st < 32; st++) {
        if (st <= 29)      asm volatile("cp.async.wait_group 2;" ::: "memory");
        else if (st == 30) asm volatile("cp.async.wait_group 1;" ::: "memory");
        else               asm volatile("cp.async.wait_group 0;" ::: "memory");
        __syncthreads();
        g_compute_stage(sb + slot * GSTG, lane, warpM, warpN, acc);
        __syncthreads();
        if (st + 3 < 32)
            g_load_stage(sb + slot * GSTG, st + 3, tid, cWh, cWl, cXh, cXl, wrow0, xrow0);
        slot = (slot == 2) ? 0 : slot + 1;
    }

    const int mat = m0 >> 10;
    float* Y = (mat == 0) ? Y0 : (mat == 1) ? Y1 : Y2;
    const int rq = lane >> 2;
    const int cq = (lane & 3) * 2;
    #pragma unroll
    for (int mt = 0; mt < 2; mt++) {
        const int rs = m0 + warpM * 32 + mt * 16 + rq;
        const int row = rs & 1023;
        const float b0 = bias[rs], b1 = bias[rs + 8];
        const size_t y0 = ((size_t)b * DM + row) * LSEQ;
        #pragma unroll
        for (int nb = 0; nb < 8; nb++) {
            const int col = n0 + warpN * 64 + nb * 8 + cq;
            float2 v0, v1;
            v0.x = acc[mt][nb][0] + b0; v0.y = acc[mt][nb][1] + b0;
            v1.x = acc[mt][nb][2] + b1; v1.y = acc[mt][nb][3] + b1;
            *(float2*)&Y[y0 + col] = v0;
            *(float2*)&Y[y0 + 8 * LSEQ + col] = v1;
        }
    }
}

// =============================================================================
// Kernel C: causal long conv — R15 dup-pair body (unchanged)
// =============================================================================
__global__ void __launch_bounds__(256)
keyconv_kernel(const float* __restrict__ kk, const float* __restrict__ kker,
               const float* __restrict__ dkey, float* __restrict__ out)
{
    extern __shared__ float dsm[];
    float* xd0 = dsm;
    float* xd1 = dsm + 8704;
    ull*   kq0 = (ull*)(dsm + 17408);
    ull*   kq1 = (ull*)(dsm + 21504);
    const int c0 = blockIdx.x * 2, b = blockIdx.y;
    const int tid = threadIdx.x;
    const size_t rb0 = ((size_t)b * DM + c0) * LSEQ;
    const size_t rb1 = rb0 + LSEQ;

    for (int i = tid; i < 8704; i += 256) { xd0[i] = 0.f; xd1[i] = 0.f; }
    __syncthreads();
    for (int i = tid; i < 2048; i += 256) {
        float add0 = (i == 0) ? dkey[c0] : 0.f;
        float add1 = (i == 0) ? dkey[c0 + 1] : 0.f;
        float k0v = kker[(size_t)c0 * LSEQ + i] + add0;
        float k1v = kker[(size_t)(c0 + 1) * LSEQ + i] + add1;
        kq0[i] = pk2(k0v, k0v);
        kq1[i] = pk2(k1v, k1v);
        int p  = 2048 + i;
        int a0 = 2 * p + ((p >> 4) << 1);
        int am = 2 * (p - 1) + (((p - 1) >> 4) << 1) + 1;
        float x0 = kk[rb0 + i];
        float x1 = kk[rb1 + i];
        xd0[a0] = x0; xd0[am] = x0;
        xd1[a0] = x1; xd1[am] = x1;
    }
    __syncthreads();

    const int wid = tid >> 5, lane = tid & 31;
    const int ch = (wid < 4) ? 0 : 1;
    const int strip = (wid < 4) ? wid : (7 - wid);
    const float* Xd = ch ? xd1 : xd0;
    const ull*   Kq = ch ? kq1 : kq0;
    const size_t rowbase = ch ? rb1 : rb0;
    const int l0 = strip * 512 + lane * 16;
    const int jmax = strip * 512 + 511;

    ull acc2[8];
    #pragma unroll
    for (int r2 = 0; r2 < 8; r2++) acc2[r2] = 0ull;

    int W0 = 2048 + l0 - 15;
    const float* Bd = Xd + (2 * W0 + ((W0 >> 4) << 1));

    for (int j0 = 0; j0 <= jmax; j0 += 16) {
        ull xv2[30];
        #pragma unroll
        for (int t = 0; t < 30; t++)
            xv2[t] = *(const ull*)(Bd + 2 * t + ((t >= 15) ? 2 : 0));
        {
            ull kr2[8];
            #pragma unroll
            for (int s = 0; s < 8; s++) kr2[s] = Kq[j0 + s];
            #pragma unroll
            for (int r2 = 0; r2 < 8; r2++)
                #pragma unroll
                for (int s = 0; s < 8; s++)
                    acc2[r2] = fma2(kr2[s], xv2[2 * r2 - s + 15], acc2[r2]);
        }
        {
            ull kr2[8];
            #pragma unroll
            for (int s = 0; s < 8; s++) kr2[s] = Kq[j0 + 8 + s];
            #pragma unroll
            for (int r2 = 0; r2 < 8; r2++)
                #pragma unroll
                for (int s = 0; s < 8; s++)
                    acc2[r2] = fma2(kr2[s], xv2[2 * r2 - s + 7], acc2[r2]);
        }
        Bd -= 34;
    }
    #pragma unroll
    for (int r2 = 0; r2 < 8; r2++) {
        float a0, a1;
        upk2(acc2[r2], a0, a1);
        out[rowbase + l0 + 2 * r2]     = a0;
        out[rowbase + l0 + 2 * r2 + 1] = a1;
    }
}

// =============================================================================
// Kernel D: kernel-weighted linear attention — R15 body verbatim, but with
// __launch_bounds__(256, 2): regs capped at 128 so TWO CTAs (16 warps) fit
// per SM (smem 84KB x2 = 168KB <= 227KB).  Fixes occ=9.6% latency starvation.
// =============================================================================
__global__ void __launch_bounds__(256, 2)
attn_kernel(const float* __restrict__ gq, const float* __restrict__ gk,
            const float* __restrict__ gv, const float* __restrict__ kerv,
            const float* __restrict__ Dp, float* __restrict__ gy)
{
    extern __shared__ float sm[];
    float* ks = sm;
    float* vs = sm + 8192;
    float* kp = sm + 16384;
    const int h = blockIdx.x, b = blockIdx.y;
    const int tid = threadIdx.x;
    const size_t base = ((size_t)b * DM + (size_t)h * HD) * LSEQ;

    for (int i = tid; i < 8192; i += 256) { ks[i] = gk[base + i]; vs[i] = gv[base + i]; }
    for (int i = tid; i < 4608; i += 256) kp[i] = 0.f;
    __syncthreads();
    for (int j = tid; j < 2048; j += 256) {
        int p = 2048 + j;
        float add = (j == 0) ? Dp[h] : 0.f;
        kp[p + (p >> 3)] = kerv[(size_t)h * LSEQ + j] + add;
    }
    __syncthreads();

    const int wid = tid >> 5, lane = tid & 31;
    const int strip = (wid < 4) ? wid : (11 - wid);
    const int l0 = strip * 256 + lane * 8;
    const int mmax = strip * 256 + 255;

    ull q2[4][4];
    #pragma unroll
    for (int d1 = 0; d1 < 4; d1++)
        #pragma unroll
        for (int r2 = 0; r2 < 4; r2++) {
            float2 qq = *(const float2*)&gq[base + (size_t)d1 * LSEQ + l0 + 2 * r2];
            q2[d1][r2] = pk2(qq.x, qq.y);
        }

    ull acc2[4][4];
    #pragma unroll
    for (int d = 0; d < 4; d++)
        #pragma unroll
        for (int r2 = 0; r2 < 4; r2++) acc2[d][r2] = 0ull;

    int W0 = 2048 + l0 - 7;
    const float* Bf = kp + (W0 + (W0 >> 3));

    for (int mb = 0; mb <= mmax; mb += 8) {
        float w15[15];
        #pragma unroll
        for (int t = 0; t < 15; t++) w15[t] = Bf[t + (t >= 7 ? 1 : 0)];

        {
            float4 kf0 = *(const float4*)&ks[mb];
            float4 kf1 = *(const float4*)&ks[2048 + mb];
            float4 kf2 = *(const float4*)&ks[4096 + mb];
            float4 kf3 = *(const float4*)&ks[6144 + mb];
            float4 vf0 = *(const float4*)&vs[mb];
            float4 vf1 = *(const float4*)&vs[2048 + mb];
            float4 vf2 = *(const float4*)&vs[4096 + mb];
            float4 vf3 = *(const float4*)&vs[6144 + mb];
            float ka[4][4] = {{kf0.x,kf0.y,kf0.z,kf0.w},{kf1.x,kf1.y,kf1.z,kf1.w},
                              {kf2.x,kf2.y,kf2.z,kf2.w},{kf3.x,kf3.y,kf3.z,kf3.w}};
            float va[4][4] = {{vf0.x,vf0.y,vf0.z,vf0.w},{vf1.x,vf1.y,vf1.z,vf1.w},
                              {vf2.x,vf2.y,vf2.z,vf2.w},{vf3.x,vf3.y,vf3.z,vf3.w}};
            #pragma unroll
            for (int i = 0; i < 4; i++) {
                ull kk0 = pk2(ka[0][i], ka[0][i]), kk1 = pk2(ka[1][i], ka[1][i]);
                ull kk2 = pk2(ka[2][i], ka[2][i]), kk3 = pk2(ka[3][i], ka[3][i]);
                ull vv0 = pk2(va[0][i], va[0][i]), vv1 = pk2(va[1][i], va[1][i]);
                ull vv2 = pk2(va[2][i], va[2][i]), vv3 = pk2(va[3][i], va[3][i]);
                #pragma unroll
                for (int r2 = 0; r2 < 4; r2++) {
                    ull s = mul2(q2[0][r2], kk0);
                    s = fma2(q2[1][r2], kk1, s);
                    s = fma2(q2[2][r2], kk2, s);
                    s = fma2(q2[3][r2], kk3, s);
                    ull kerp = pk2(w15[2 * r2 - i + 7], w15[2 * r2 - i + 8]);
                    ull w = mul2(s, kerp);
                    acc2[0][r2] = fma2(w, vv0, acc2[0][r2]);
                    acc2[1][r2] = fma2(w, vv1, acc2[1][r2]);
                    acc2[2][r2] = fma2(w, vv2, acc2[2][r2]);
                    acc2[3][r2] = fma2(w, vv3, acc2[3][r2]);
                }
            }
        }
        {
            float4 kf0 = *(const float4*)&ks[mb + 4];
            float4 kf1 = *(const float4*)&ks[2048 + mb + 4];
            float4 kf2 = *(const float4*)&ks[4096 + mb + 4];
            float4 kf3 = *(const float4*)&ks[6144 + mb + 4];
            float4 vf0 = *(const float4*)&vs[mb + 4];
            float4 vf1 = *(const float4*)&vs[2048 + mb + 4];
            float4 vf2 = *(const float4*)&vs[4096 + mb + 4];
            float4 vf3 = *(const float4*)&vs[6144 + mb + 4];
            float ka[4][4] = {{kf0.x,kf0.y,kf0.z,kf0.w},{kf1.x,kf1.y,kf1.z,kf1.w},
                              {kf2.x,kf2.y,kf2.z,kf2.w},{kf3.x,kf3.y,kf3.z,kf3.w}};
            float va[4][4] = {{vf0.x,vf0.y,vf0.z,vf0.w},{vf1.x,vf1.y,vf1.z,vf1.w},
                              {vf2.x,vf2.y,vf2.z,vf2.w},{vf3.x,vf3.y,vf3.z,vf3.w}};
            #pragma unroll
            for (int i = 0; i < 4; i++) {
                ull kk0 = pk2(ka[0][i], ka[0][i]), kk1 = pk2(ka[1][i], ka[1][i]);
                ull kk2 = pk2(ka[2][i], ka[2][i]), kk3 = pk2(ka[3][i], ka[3][i]);
                ull vv0 = pk2(va[0][i], va[0][i]), vv1 = pk2(va[1][i], va[1][i]);
                ull vv2 = pk2(va[2][i], va[2][i]), vv3 = pk2(va[3][i], va[3][i]);
                #pragma unroll
                for (int r2 = 0; r2 < 4; r2++) {
                    ull s = mul2(q2[0][r2], kk0);
                    s = fma2(q2[1][r2], kk1, s);
                    s = fma2(q2[2][r2], kk2, s);
                    s = fma2(q2[3][r2], kk3, s);
                    ull kerp = pk2(w15[2 * r2 - i + 3], w15[2 * r2 - i + 4]);
                    ull w = mul2(s, kerp);
                    acc2[0][r2] = fma2(w, vv0, acc2[0][r2]);
                    acc2[1][r2] = fma2(w, vv1, acc2[1][r2]);
                    acc2[2][r2] = fma2(w, vv2, acc2[2][r2]);
                    acc2[3][r2] = fma2(w, vv3, acc2[3][r2]);
                }
            }
        }
        Bf -= 9;
    }

    float acc[4][8];
    #pragma unroll
    for (int d = 0; d < 4; d++)
        #pragma unroll
        for (int r2 = 0; r2 < 4; r2++)
            upk2(acc2[d][r2], acc[d][2 * r2], acc[d][2 * r2 + 1]);

    #pragma unroll
    for (int d2 = 0; d2 < 4; d2++) {
        size_t orow = ((size_t)b * DM + (size_t)d2 * HH + h) * LSEQ + l0;
        #pragma unroll
        for (int r = 0; r < 8; r++) {
            float x = acc[d2][r];
            gy[orow + r] = 0.5f * x * (1.f + erff(x * 0.70710678118654752f));
        }
    }
}

// =============================================================================
extern "C" void kernel_launch(void* const* d_in, const int* in_sizes, int n_in,
                              void* d_out, int out_size)
{
    const float* u       = (const float*)d_in[0];
    const float* q_w     = (const float*)d_in[1];
    const float* q_b     = (const float*)d_in[2];
    const float* k_w     = (const float*)d_in[3];
    const float* k_b     = (const float*)d_in[4];
    const float* v_w     = (const float*)d_in[5];
    const float* v_b     = (const float*)d_in[6];
    const float* kkey_in = (const float*)d_in[7];
    const float* kv_in   = (const float*)d_in[8];
    const float* D_key   = (const float*)d_in[9];
    const float* Dh      = (const float*)d_in[10];
    const float* pw_w    = (const float*)d_in[11];
    const float* pw_b    = (const float*)d_in[12];
    float* out = (float*)d_out;

    float *kkey, *kvk, *q, *k, *v, *kc, *y, *bias;
    __nv_bfloat16 *wh, *wl, *xh, *xl;
    cudaGetSymbolAddress((void**)&kkey, g_kkey);
    cudaGetSymbolAddress((void**)&kvk,  g_kvker);
    cudaGetSymbolAddress((void**)&q,    g_q);
    cudaGetSymbolAddress((void**)&k,    g_k);
    cudaGetSymbolAddress((void**)&v,    g_v);
    cudaGetSymbolAddress((void**)&kc,   g_kc);
    cudaGetSymbolAddress((void**)&y,    g_y);
    cudaGetSymbolAddress((void**)&bias, g_bias);
    cudaGetSymbolAddress((void**)&wh,   g_wh);
    cudaGetSymbolAddress((void**)&wl,   g_wl);
    cudaGetSymbolAddress((void**)&xh,   g_xh);
    cudaGetSymbolAddress((void**)&xl,   g_xl);

    const int ATT_SMEM = (8192 + 8192 + 4608) * (int)sizeof(float);   // 83968
    const int KC_SMEM  = 25600 * (int)sizeof(float);                  // 102400
    cudaFuncSetAttribute(attn_kernel, cudaFuncAttributeMaxDynamicSharedMemorySize, ATT_SMEM);
    cudaFuncSetAttribute(keyconv_kernel, cudaFuncAttributeMaxDynamicSharedMemorySize, KC_SMEM);
    cudaFuncSetAttribute(mma_gemm, cudaFuncAttributeMaxDynamicSharedMemorySize, 3 * GSTG);

    const size_t WN = (size_t)DM * DM;

    // attn stays the 4th launch (= profiled).
    prep_all<<<25868, 256>>>(k_w, q_w, v_w, pw_w, wh, wl,
                             k_b, q_b, v_b, bias,
                             kkey_in, kv_in, kkey, kvk,
                             u, xh, xl);                                 // 1
    mma_gemm<<<dim3(LSEQ / 128, 24, BB), 256, 3 * GSTG>>>(               // 2
        wh, wl, xh, xl, bias, 0, k, q, v);
    keyconv_kernel<<<dim3(DM / 2, BB), 256, KC_SMEM>>>(k, kkey, D_key, kc); // 3
    attn_kernel<<<dim3(HH, BB), 256, ATT_SMEM>>>(q, kc, v, kvk, Dh, y);  // 4 (profiled)
    trans_split<<<dim3(LSEQ / 32, DM / 32, BB), 256>>>(y, xh, xl);       // 5
    mma_gemm<<<dim3(LSEQ / 128, 8, BB), 256, 3 * GSTG>>>(                // 6
        wh + 3 * WN, wl + 3 * WN, xh, xl, pw_b, 0, out, out, out);
}